// round 8
// baseline (speedup 1.0000x reference)
#include <cuda_runtime.h>
#include <cuda_fp16.h>

#define DEV_INLINE __device__ __forceinline__

// ---------------- problem constants ----------------
constexpr int BATCH = 4;
constexpr int SEQ   = 2048;
constexpr int DIM   = 1024;            // D == DQKV
constexpr int MTOK  = BATCH * SEQ;     // 8192

// ---------------- GEMM tiling ----------------
constexpr int BM = 128, BN = 256, BK = 32, SPAD = 8;
constexpr int LDS = BK + SPAD;                 // 40 halfs per smem row
constexpr int AE  = BM * LDS;                  // 5120  elems per A tile
constexpr int BE  = BN * LDS;                  // 10240 elems per B tile
constexpr int WM = 64, WN = 64;                // warp tile (8 warps: 2 x 4)
constexpr int EPI_PITCH = 260;                 // fp32 words per staged row
constexpr int EPI_BYTES = 64 * EPI_PITCH * 4;  // 66560
constexpr int STAGE_PLAIN = (AE + BE) * 2;         // 30720 B
constexpr int STAGE_SPLIT = (2 * AE + BE) * 2;     // 40960 B
constexpr int SM_PLAIN = (2 * STAGE_PLAIN > EPI_BYTES) ? 2 * STAGE_PLAIN : EPI_BYTES; // 66560
constexpr int SM_SPLIT = (2 * STAGE_SPLIT > EPI_BYTES) ? 2 * STAGE_SPLIT : EPI_BYTES; // 81920

// ---------------- scratch (static device allocations; no cudaMalloc) ----------------
__device__ __align__(16) __half g_xh[MTOK * DIM];
__device__ __align__(16) __half g_xl[MTOK * DIM];
__device__ __align__(16) __half g_wth[3 * DIM * DIM];        // Wt[n][k] fp16
__device__ __align__(16) __half g_q[MTOK * DIM];
__device__ __align__(16) __half g_k[MTOK * DIM];
__device__ __align__(16) __half g_vt[BATCH * DIM * SEQ];     // V^T [b][d][i]
__device__ __align__(16) float  g_s[(size_t)BATCH * SEQ * SEQ];
__device__ __align__(16) __half g_p[(size_t)BATCH * SEQ * SEQ];

// ---------------- PTX helpers ----------------
DEV_INLINE void cp16(unsigned dst, const void* src) {
    asm volatile("cp.async.cg.shared.global [%0], [%1], 16;\n" :: "r"(dst), "l"(src));
}
DEV_INLINE void cp_commit() { asm volatile("cp.async.commit_group;\n" ::: "memory"); }
template <int N> DEV_INLINE void cp_wait() {
    asm volatile("cp.async.wait_group %0;\n" :: "n"(N) : "memory");
}
DEV_INLINE void ldsm4(unsigned addr, unsigned& r0, unsigned& r1, unsigned& r2, unsigned& r3) {
    asm volatile("ldmatrix.sync.aligned.m8n8.x4.shared.b16 {%0,%1,%2,%3}, [%4];\n"
        : "=r"(r0), "=r"(r1), "=r"(r2), "=r"(r3) : "r"(addr));
}
DEV_INLINE void ldsm2(unsigned addr, unsigned& r0, unsigned& r1) {
    asm volatile("ldmatrix.sync.aligned.m8n8.x2.shared.b16 {%0,%1}, [%2];\n"
        : "=r"(r0), "=r"(r1) : "r"(addr));
}
DEV_INLINE void mma16816(float c[4], const unsigned a[4], const unsigned b[2]) {
    asm volatile(
        "mma.sync.aligned.m16n8k16.row.col.f32.f16.f16.f32 "
        "{%0,%1,%2,%3}, {%4,%5,%6,%7}, {%8,%9}, {%0,%1,%2,%3};\n"
        : "+f"(c[0]), "+f"(c[1]), "+f"(c[2]), "+f"(c[3])
        : "r"(a[0]), "r"(a[1]), "r"(a[2]), "r"(a[3]), "r"(b[0]), "r"(b[1]));
}

// ---------------- GEMM parameter block ----------------
struct GemmP {
    const __half* A;  const __half* Al;     // Al used only when SPLIT
    const __half* B;
    float* C;
    __half* q; __half* k; __half* vt;
    long long sAz, sBz, sCz;                // per-batch (blockIdx.z) element strides
    int lda, ldb, ldc, K;
    float scale;
};

// MODE 0: QKV projection epilogue (fp16 Q/K row-major + V transposed)
// MODE 1: scores epilogue (fp32 * scale)
// MODE 2: output epilogue (fp32)
template <int MODE, bool SPLIT>
__global__ __launch_bounds__(256, 1) void gemm_kernel(GemmP p) {
    extern __shared__ char smraw[];
    const unsigned su = (unsigned)__cvta_generic_to_shared(smraw);
    constexpr int STAGE_B = SPLIT ? STAGE_SPLIT : STAGE_PLAIN;
    constexpr int BOFF = (SPLIT ? 2 * AE : AE) * 2;   // byte offset of B tile in stage

    const int tid = threadIdx.x;
    const int lane = tid & 31, wid = tid >> 5;
    const int bm = blockIdx.y * BM;
    const int bn = blockIdx.x * BN;

    const __half* A  = p.A + (size_t)blockIdx.z * p.sAz;
    const __half* B  = p.B + (size_t)blockIdx.z * p.sBz;
    const __half* Al = SPLIT ? (p.Al + (size_t)blockIdx.z * p.sAz) : nullptr;

    // ---- stage loader: A = 512 16B-chunks, B = 1024 chunks, (Al = 512) ----
    auto load_stage = [&](int st, int k0) {
        const unsigned sA = su + (unsigned)(st * STAGE_B);
        const unsigned sB = sA + (unsigned)BOFF;
#pragma unroll
        for (int i = 0; i < 2; i++) {
            int ch = tid + i * 256, row = ch >> 2, cc = ch & 3;
            cp16(sA + (unsigned)((row * LDS + cc * 8) * 2),
                 A + (size_t)(bm + row) * p.lda + k0 + cc * 8);
        }
        if (SPLIT) {
            const unsigned sAl = sA + (unsigned)(AE * 2);
#pragma unroll
            for (int i = 0; i < 2; i++) {
                int ch = tid + i * 256, row = ch >> 2, cc = ch & 3;
                cp16(sAl + (unsigned)((row * LDS + cc * 8) * 2),
                     Al + (size_t)(bm + row) * p.lda + k0 + cc * 8);
            }
        }
#pragma unroll
        for (int i = 0; i < 4; i++) {
            int ch = tid + i * 256, row = ch >> 2, cc = ch & 3;
            cp16(sB + (unsigned)((row * LDS + cc * 8) * 2),
                 B + (size_t)(bn + row) * p.ldb + k0 + cc * 8);
        }
    };

    const int wm0 = (wid & 1) * WM;      // 0 / 64
    const int wn0 = (wid >> 1) * WN;     // 0 / 64 / 128 / 192

    int aoff[4], boff[8];
#pragma unroll
    for (int mt = 0; mt < 4; mt++)
        aoff[mt] = (wm0 + mt * 16 + (lane & 15)) * LDS + ((lane >> 4) << 3);
#pragma unroll
    for (int nt = 0; nt < 8; nt++)
        boff[nt] = (wn0 + nt * 8 + (lane & 7)) * LDS + (((lane >> 3) & 1) << 3);

    float acc[4][8][4];
#pragma unroll
    for (int mt = 0; mt < 4; mt++)
#pragma unroll
        for (int nt = 0; nt < 8; nt++)
#pragma unroll
            for (int i = 0; i < 4; i++) acc[mt][nt][i] = 0.0f;

    const int KT = p.K / BK;
    load_stage(0, 0);
    cp_commit();

    for (int kt = 0; kt < KT; kt++) {
        if (kt + 1 < KT) {
            load_stage((kt + 1) & 1, (kt + 1) * BK);
            cp_commit();
            cp_wait<1>();
        } else {
            cp_wait<0>();
        }
        __syncthreads();

        const int st = kt & 1;
        const unsigned uA  = su + (unsigned)(st * STAGE_B);
        const unsigned uB  = uA + (unsigned)BOFF;
        const unsigned uAl = uA + (unsigned)(AE * 2);

#pragma unroll
        for (int kk = 0; kk < BK; kk += 16) {
            unsigned af[4][4], afl[4][4], bf[8][2];
#pragma unroll
            for (int mt = 0; mt < 4; mt++)
                ldsm4(uA + (unsigned)((aoff[mt] + kk) * 2),
                      af[mt][0], af[mt][1], af[mt][2], af[mt][3]);
            if (SPLIT) {
#pragma unroll
                for (int mt = 0; mt < 4; mt++)
                    ldsm4(uAl + (unsigned)((aoff[mt] + kk) * 2),
                          afl[mt][0], afl[mt][1], afl[mt][2], afl[mt][3]);
            }
#pragma unroll
            for (int nt = 0; nt < 8; nt++)
                ldsm2(uB + (unsigned)((boff[nt] + kk) * 2), bf[nt][0], bf[nt][1]);
#pragma unroll
            for (int mt = 0; mt < 4; mt++) {
#pragma unroll
                for (int nt = 0; nt < 8; nt++) {
                    mma16816(acc[mt][nt], af[mt], bf[nt]);
                    if (SPLIT) mma16816(acc[mt][nt], afl[mt], bf[nt]);  // x_lo * w_hi
                }
            }
        }
        __syncthreads();
    }

    // ---------------- epilogue: stage 64x256 halves through smem, coalesced stores ----
    float* smf = (float*)smraw;
    const int g = lane >> 2, tg = lane & 3;

#pragma unroll
    for (int h = 0; h < 2; h++) {
        if (wm0 == h * 64) {
#pragma unroll
            for (int mt = 0; mt < 4; mt++) {
#pragma unroll
                for (int nt = 0; nt < 8; nt++) {
                    const int rl = mt * 16 + g;
                    const int c  = wn0 + nt * 8 + tg * 2;
                    const float* a = acc[mt][nt];
                    smf[rl * EPI_PITCH + c]           = a[0];
                    smf[rl * EPI_PITCH + c + 1]       = a[1];
                    smf[(rl + 8) * EPI_PITCH + c]     = a[2];
                    smf[(rl + 8) * EPI_PITCH + c + 1] = a[3];
                }
            }
        }
        __syncthreads();

        if (MODE == 1 || MODE == 2) {
            float* C = p.C + (size_t)blockIdx.z * p.sCz;
#pragma unroll
            for (int it = 0; it < 8; it++) {
                const int row = it * 8 + wid;
                const int gr = bm + h * 64 + row;
#pragma unroll
                for (int cp = 0; cp < 2; cp++) {
                    float4 v = *(float4*)&smf[row * EPI_PITCH + cp * 128 + lane * 4];
                    if (MODE == 1) { v.x *= p.scale; v.y *= p.scale; v.z *= p.scale; v.w *= p.scale; }
                    *(float4*)&C[(size_t)gr * p.ldc + bn + cp * 128 + lane * 4] = v;
                }
            }
        } else {
            if (bn < 2 * DIM) {                         // Q or K (row-major fp16)
                __half* dst = (bn < DIM) ? p.q : p.k;
                const int cb0 = (bn < DIM) ? bn : bn - DIM;
#pragma unroll
                for (int it = 0; it < 8; it++) {
                    const int row = it * 8 + wid;
                    const int gr = bm + h * 64 + row;
#pragma unroll
                    for (int cp = 0; cp < 2; cp++) {
                        float4 v = *(float4*)&smf[row * EPI_PITCH + cp * 128 + lane * 4];
                        __half2 h0 = __floats2half2_rn(v.x, v.y);
                        __half2 h1 = __floats2half2_rn(v.z, v.w);
                        uint2 u;
                        u.x = *reinterpret_cast<unsigned*>(&h0);
                        u.y = *reinterpret_cast<unsigned*>(&h1);
                        *(uint2*)&dst[(size_t)gr * DIM + cb0 + cp * 128 + lane * 4] = u;
                    }
                }
            } else {                                    // V transposed: vt[b][d][i]
                const int d0 = bn - 2 * DIM;
                const int b  = bm >> 11;
                const int i0 = (bm & (SEQ - 1)) + h * 64;
#pragma unroll
                for (int dd = 0; dd < 32; dd++) {
                    const int d = dd * 8 + wid;
                    const float f0 = smf[(lane * 2) * EPI_PITCH + d];
                    const float f1 = smf[(lane * 2 + 1) * EPI_PITCH + d];
                    __half2 hv = __floats2half2_rn(f0, f1);
                    *(__half2*)&p.vt[((size_t)b * DIM + d0 + d) * SEQ + i0 + lane * 2] = hv;
                }
            }
        }
        __syncthreads();
    }
}

// ---------------- prep: x -> fp16 hi/lo split ----------------
__global__ void convert_x_kernel(const float* __restrict__ x,
                                 __half* __restrict__ xh, __half* __restrict__ xl) {
    size_t i = (size_t)blockIdx.x * blockDim.x + threadIdx.x;
    float4 v = ((const float4*)x)[i];
    __half h0 = __float2half(v.x), h1 = __float2half(v.y);
    __half h2 = __float2half(v.z), h3 = __float2half(v.w);
    ((__half2*)xh)[2 * i]     = __halves2half2(h0, h1);
    ((__half2*)xh)[2 * i + 1] = __halves2half2(h2, h3);
    __half l0 = __float2half(v.x - __half2float(h0));
    __half l1 = __float2half(v.y - __half2float(h1));
    __half l2 = __float2half(v.z - __half2float(h2));
    __half l3 = __float2half(v.w - __half2float(h3));
    ((__half2*)xl)[2 * i]     = __halves2half2(l0, l1);
    ((__half2*)xl)[2 * i + 1] = __halves2half2(l2, l3);
}

// ---------------- prep: w[k][n] -> Wt[n][k] fp16 (tiled transpose) ----------------
__global__ void prep_w_kernel(const float* __restrict__ w, __half* __restrict__ wh) {
    __shared__ float t[32][33];
    const int k0 = blockIdx.y * 32, n0 = blockIdx.x * 32;
#pragma unroll
    for (int r = 0; r < 32; r += 8)
        t[threadIdx.y + r][threadIdx.x] =
            w[(size_t)(k0 + threadIdx.y + r) * DIM + n0 + threadIdx.x];
    __syncthreads();
#pragma unroll
    for (int r = 0; r < 32; r += 8) {
        const int n = n0 + threadIdx.y + r;
        const int k = k0 + threadIdx.x;
        wh[(size_t)n * DIM + k] = __float2half(t[threadIdx.x][threadIdx.y + r]);
    }
}

// ---------------- softmax: rows of 2048, fp32 in -> fp16 probs ----------------
__global__ __launch_bounds__(256) void softmax_kernel(const float* __restrict__ S,
                                                      __half* __restrict__ P) {
    __shared__ float red[8];
    const size_t row = blockIdx.x;
    const float* sr = S + row * SEQ;
    __half* pr = P + row * SEQ;
    const int tid = threadIdx.x;

    float v[8];
    float m = -1e30f;
#pragma unroll
    for (int j = 0; j < 8; j++) { v[j] = sr[tid + j * 256]; m = fmaxf(m, v[j]); }
#pragma unroll
    for (int o = 16; o > 0; o >>= 1) m = fmaxf(m, __shfl_xor_sync(0xffffffffu, m, o));
    if ((tid & 31) == 0) red[tid >> 5] = m;
    __syncthreads();
    float M = red[0];
#pragma unroll
    for (int wv = 1; wv < 8; wv++) M = fmaxf(M, red[wv]);
    __syncthreads();

    float sum = 0.0f;
#pragma unroll
    for (int j = 0; j < 8; j++) { v[j] = __expf(v[j] - M); sum += v[j]; }
#pragma unroll
    for (int o = 16; o > 0; o >>= 1) sum += __shfl_xor_sync(0xffffffffu, sum, o);
    if ((tid & 31) == 0) red[tid >> 5] = sum;
    __syncthreads();
    float tot = 0.0f;
#pragma unroll
    for (int wv = 0; wv < 8; wv++) tot += red[wv];
    const float inv = 1.0f / tot;
#pragma unroll
    for (int j = 0; j < 8; j++) pr[tid + j * 256] = __float2half(v[j] * inv);
}

// ---------------- launch ----------------
extern "C" void kernel_launch(void* const* d_in, const int* in_sizes, int n_in,
                              void* d_out, int out_size) {
    const float* x = (const float*)d_in[0];
    const float* w[3] = { (const float*)d_in[1], (const float*)d_in[2], (const float*)d_in[3] };
    float* out = (float*)d_out;

    void *xh, *xl, *wth, *q, *k, *vt, *s, *pbuf;
    cudaGetSymbolAddress(&xh, g_xh);
    cudaGetSymbolAddress(&xl, g_xl);
    cudaGetSymbolAddress(&wth, g_wth);
    cudaGetSymbolAddress(&q, g_q);
    cudaGetSymbolAddress(&k, g_k);
    cudaGetSymbolAddress(&vt, g_vt);
    cudaGetSymbolAddress(&s, g_s);
    cudaGetSymbolAddress(&pbuf, g_p);

    cudaFuncSetAttribute(gemm_kernel<0, true>,
                         cudaFuncAttributeMaxDynamicSharedMemorySize, SM_SPLIT);
    cudaFuncSetAttribute(gemm_kernel<1, false>,
                         cudaFuncAttributeMaxDynamicSharedMemorySize, SM_PLAIN);
    cudaFuncSetAttribute(gemm_kernel<2, false>,
                         cudaFuncAttributeMaxDynamicSharedMemorySize, SM_PLAIN);

    // 1) input split to fp16 hi/lo
    convert_x_kernel<<<(MTOK * DIM / 4) / 256, 256>>>(x, (__half*)xh, (__half*)xl);

    // 2) weight transpose to fp16 Wt[3072][1024]
    for (int i = 0; i < 3; i++)
        prep_w_kernel<<<dim3(32, 32), dim3(32, 8)>>>(
            w[i], (__half*)wth + (size_t)i * DIM * DIM);

    // 3) fused QKV projection: (xh + xl) * Wh  -> Q/K fp16 + V^T fp16
    {
        GemmP p{};
        p.A = (__half*)xh;  p.Al = (__half*)xl;
        p.B = (__half*)wth;
        p.q = (__half*)q; p.k = (__half*)k; p.vt = (__half*)vt;
        p.lda = DIM; p.ldb = DIM; p.K = DIM; p.scale = 1.0f;
        gemm_kernel<0, true><<<dim3(3 * DIM / BN, MTOK / BM, 1), 256, SM_SPLIT>>>(p);
    }

    // 4) scores = Q K^T / 32 (per batch)
    {
        GemmP p{};
        p.A = (__half*)q; p.B = (__half*)k; p.C = (float*)s;
        p.sAz = (long long)SEQ * DIM; p.sBz = (long long)SEQ * DIM;
        p.sCz = (long long)SEQ * SEQ;
        p.lda = DIM; p.ldb = DIM; p.ldc = SEQ; p.K = DIM;
        p.scale = 1.0f / 32.0f;
        gemm_kernel<1, false><<<dim3(SEQ / BN, SEQ / BM, BATCH), 256, SM_PLAIN>>>(p);
    }

    // 5) softmax rows -> fp16 P
    softmax_kernel<<<BATCH * SEQ, 256>>>((const float*)s, (__half*)pbuf);

    // 6) out = P V (per batch)
    {
        GemmP p{};
        p.A = (__half*)pbuf; p.B = (__half*)vt; p.C = out;
        p.sAz = (long long)SEQ * SEQ; p.sBz = (long long)DIM * SEQ;
        p.sCz = (long long)SEQ * DIM;
        p.lda = SEQ; p.ldb = SEQ; p.ldc = DIM; p.K = SEQ;
        p.scale = 1.0f;
        gemm_kernel<2, false><<<dim3(DIM / BN, SEQ / BM, BATCH), 256, SM_PLAIN>>>(p);
    }
}

// round 10
// speedup vs baseline: 1.4086x; 1.4086x over previous
#include <cuda_runtime.h>
#include <cuda_fp16.h>

#define DEV_INLINE __device__ __forceinline__

// ---------------- problem constants ----------------
constexpr int BATCH = 4;
constexpr int SEQ   = 2048;
constexpr int DIM   = 1024;            // D == DQKV
constexpr int MTOK  = BATCH * SEQ;     // 8192

// ---------------- GEMM tiling (R2-proven config) ----------------
constexpr int BM = 128, BN = 128, BK = 32, SPAD = 8;
constexpr int LDS = BK + SPAD;                 // 40 halfs per smem row
constexpr int TILE_E = BM * LDS;               // 5120 elems per operand tile
constexpr int WM = 64, WN = 32;                // warp tile (8 warps: 2 x 4)
constexpr int EPI_PITCH = 132;                 // fp32 words per staged row
constexpr int EPI_BYTES = 64 * EPI_PITCH * 4;  // 33792 (one 64-row half)
constexpr int SM_PLAIN = 2 * 2 * TILE_E * 2;   // 40960 B (A,B x 2 stages)
constexpr int SM_SPLIT = 2 * 3 * TILE_E * 2;   // 61440 B (Ah,Al,B x 2 stages)
static_assert(EPI_BYTES <= SM_PLAIN, "epilogue staging fits");

// ---------------- scratch (static device allocations; no cudaMalloc) ----------------
__device__ __align__(16) __half g_xh[MTOK * DIM];
__device__ __align__(16) __half g_xl[MTOK * DIM];
__device__ __align__(16) __half g_wth[3 * DIM * DIM];        // Wt[n][k] fp16
__device__ __align__(16) __half g_q[MTOK * DIM];
__device__ __align__(16) __half g_k[MTOK * DIM];
__device__ __align__(16) __half g_vt[BATCH * DIM * SEQ];     // V^T [b][d][i]
__device__ __align__(16) float  g_s[(size_t)BATCH * SEQ * SEQ];
__device__ __align__(16) __half g_p[(size_t)BATCH * SEQ * SEQ];

// ---------------- PTX helpers ----------------
DEV_INLINE void cp16(unsigned dst, const void* src) {
    asm volatile("cp.async.cg.shared.global [%0], [%1], 16;\n" :: "r"(dst), "l"(src));
}
DEV_INLINE void cp_commit() { asm volatile("cp.async.commit_group;\n" ::: "memory"); }
template <int N> DEV_INLINE void cp_wait() {
    asm volatile("cp.async.wait_group %0;\n" :: "n"(N) : "memory");
}
DEV_INLINE void ldsm4(unsigned addr, unsigned& r0, unsigned& r1, unsigned& r2, unsigned& r3) {
    asm volatile("ldmatrix.sync.aligned.m8n8.x4.shared.b16 {%0,%1,%2,%3}, [%4];\n"
        : "=r"(r0), "=r"(r1), "=r"(r2), "=r"(r3) : "r"(addr));
}
DEV_INLINE void ldsm2(unsigned addr, unsigned& r0, unsigned& r1) {
    asm volatile("ldmatrix.sync.aligned.m8n8.x2.shared.b16 {%0,%1}, [%2];\n"
        : "=r"(r0), "=r"(r1) : "r"(addr));
}
DEV_INLINE void mma16816(float c[4], const unsigned a[4], const unsigned b[2]) {
    asm volatile(
        "mma.sync.aligned.m16n8k16.row.col.f32.f16.f16.f32 "
        "{%0,%1,%2,%3}, {%4,%5,%6,%7}, {%8,%9}, {%0,%1,%2,%3};\n"
        : "+f"(c[0]), "+f"(c[1]), "+f"(c[2]), "+f"(c[3])
        : "r"(a[0]), "r"(a[1]), "r"(a[2]), "r"(a[3]), "r"(b[0]), "r"(b[1]));
}

// ---------------- GEMM parameter block ----------------
struct GemmP {
    const __half* A;  const __half* Al;     // Al used only when SPLIT
    const __half* B;
    float* C;
    __half* q; __half* k; __half* vt;
    long long sAz, sBz, sCz;                // per-batch (blockIdx.z) element strides
    int lda, ldb, ldc, K;
    float scale;
};

// MODE 0: QKV projection epilogue (fp16 Q/K row-major + V transposed)
// MODE 1: scores epilogue (fp32 * scale)
// MODE 2: output epilogue (fp32)
template <int MODE, bool SPLIT>
__global__ __launch_bounds__(256, 1) void gemm_kernel(GemmP p) {
    extern __shared__ char smraw[];
    const unsigned su = (unsigned)__cvta_generic_to_shared(smraw);
    constexpr int STAGE_B = (SPLIT ? 3 : 2) * TILE_E * 2;   // bytes per stage
    constexpr int BOFF = (SPLIT ? 2 : 1) * TILE_E * 2;      // B-tile byte offset in stage

    const int tid = threadIdx.x;
    const int lane = tid & 31, wid = tid >> 5;
    const int bm = blockIdx.y * BM;
    const int bn = blockIdx.x * BN;

    const __half* A  = p.A + (size_t)blockIdx.z * p.sAz;
    const __half* B  = p.B + (size_t)blockIdx.z * p.sBz;
    const __half* Al = SPLIT ? (p.Al + (size_t)blockIdx.z * p.sAz) : nullptr;

    // gmem->smem: 512 16B chunks per tile, 2 per thread
    const int r0 = tid >> 2,         c0 = (tid & 3) * 8;
    const int r1 = (tid + 256) >> 2, c1 = ((tid + 256) & 3) * 8;

    auto load_stage = [&](int st, int k0) {
        const unsigned uA = su + (unsigned)(st * STAGE_B);
        const unsigned uB = uA + (unsigned)BOFF;
        cp16(uA + (r0 * LDS + c0) * 2, A + (size_t)(bm + r0) * p.lda + k0 + c0);
        cp16(uA + (r1 * LDS + c1) * 2, A + (size_t)(bm + r1) * p.lda + k0 + c1);
        if (SPLIT) {
            const unsigned uAl = uA + (unsigned)(TILE_E * 2);
            cp16(uAl + (r0 * LDS + c0) * 2, Al + (size_t)(bm + r0) * p.lda + k0 + c0);
            cp16(uAl + (r1 * LDS + c1) * 2, Al + (size_t)(bm + r1) * p.lda + k0 + c1);
        }
        cp16(uB + (r0 * LDS + c0) * 2, B + (size_t)(bn + r0) * p.ldb + k0 + c0);
        cp16(uB + (r1 * LDS + c1) * 2, B + (size_t)(bn + r1) * p.ldb + k0 + c1);
    };

    const int wm0 = (wid & 1) * WM;     // 0 / 64
    const int wn0 = (wid >> 1) * WN;    // 0 / 32 / 64 / 96

    int aoff[4], boff[4];
#pragma unroll
    for (int mt = 0; mt < 4; mt++)
        aoff[mt] = (wm0 + mt * 16 + (lane & 15)) * LDS + ((lane >> 4) << 3);
#pragma unroll
    for (int nt = 0; nt < 4; nt++)
        boff[nt] = (wn0 + nt * 8 + (lane & 7)) * LDS + (((lane >> 3) & 1) << 3);

    float acc[4][4][4];
#pragma unroll
    for (int mt = 0; mt < 4; mt++)
#pragma unroll
        for (int nt = 0; nt < 4; nt++)
#pragma unroll
            for (int i = 0; i < 4; i++) acc[mt][nt][i] = 0.0f;

    const int KT = p.K / BK;
    load_stage(0, 0);
    cp_commit();

    for (int kt = 0; kt < KT; kt++) {
        if (kt + 1 < KT) {
            load_stage((kt + 1) & 1, (kt + 1) * BK);
            cp_commit();
            cp_wait<1>();
        } else {
            cp_wait<0>();
        }
        __syncthreads();

        const int st = kt & 1;
        const unsigned uA  = su + (unsigned)(st * STAGE_B);
        const unsigned uB  = uA + (unsigned)BOFF;
        const unsigned uAl = uA + (unsigned)(TILE_E * 2);

#pragma unroll
        for (int kk = 0; kk < BK; kk += 16) {
            unsigned af[4][4], afl[4][4], bf[4][2];
#pragma unroll
            for (int mt = 0; mt < 4; mt++)
                ldsm4(uA + (unsigned)((aoff[mt] + kk) * 2),
                      af[mt][0], af[mt][1], af[mt][2], af[mt][3]);
            if (SPLIT) {
#pragma unroll
                for (int mt = 0; mt < 4; mt++)
                    ldsm4(uAl + (unsigned)((aoff[mt] + kk) * 2),
                          afl[mt][0], afl[mt][1], afl[mt][2], afl[mt][3]);
            }
#pragma unroll
            for (int nt = 0; nt < 4; nt++)
                ldsm2(uB + (unsigned)((boff[nt] + kk) * 2), bf[nt][0], bf[nt][1]);
#pragma unroll
            for (int mt = 0; mt < 4; mt++) {
#pragma unroll
                for (int nt = 0; nt < 4; nt++) {
                    mma16816(acc[mt][nt], af[mt], bf[nt]);
                    if (SPLIT) mma16816(acc[mt][nt], afl[mt], bf[nt]);   // x_lo * w_hi
                }
            }
        }
        __syncthreads();
    }

    // ---------------- epilogue: stage 64x128 fp32 halves through smem ----------------
    float* smf = (float*)smraw;
    const int g = lane >> 2, tg = lane & 3;

#pragma unroll
    for (int h = 0; h < 2; h++) {
        if (wm0 == h * 64) {
#pragma unroll
            for (int mt = 0; mt < 4; mt++) {
#pragma unroll
                for (int nt = 0; nt < 4; nt++) {
                    const int rl = mt * 16 + g;
                    const int c  = wn0 + nt * 8 + tg * 2;
                    const float* a = acc[mt][nt];
                    smf[rl * EPI_PITCH + c]           = a[0];
                    smf[rl * EPI_PITCH + c + 1]       = a[1];
                    smf[(rl + 8) * EPI_PITCH + c]     = a[2];
                    smf[(rl + 8) * EPI_PITCH + c + 1] = a[3];
                }
            }
        }
        __syncthreads();

        if (MODE == 1 || MODE == 2) {
            float* C = p.C + (size_t)blockIdx.z * p.sCz;
#pragma unroll
            for (int it = 0; it < 8; it++) {
                const int row = it * 8 + wid;
                const int gr = bm + h * 64 + row;
                float4 v = *(float4*)&smf[row * EPI_PITCH + lane * 4];
                if (MODE == 1) { v.x *= p.scale; v.y *= p.scale; v.z *= p.scale; v.w *= p.scale; }
                *(float4*)&C[(size_t)gr * p.ldc + bn + lane * 4] = v;
            }
        } else {
            if (bn < 2 * DIM) {                          // Q or K (row-major fp16)
                __half* dst = (bn < DIM) ? p.q : p.k;
                const int cb0 = (bn < DIM) ? bn : bn - DIM;
#pragma unroll
                for (int it = 0; it < 8; it++) {
                    const int row = it * 8 + wid;
                    const int gr = bm + h * 64 + row;
                    float4 v = *(float4*)&smf[row * EPI_PITCH + lane * 4];
                    __half2 h0 = __floats2half2_rn(v.x, v.y);
                    __half2 h1 = __floats2half2_rn(v.z, v.w);
                    uint2 u;
                    u.x = *reinterpret_cast<unsigned*>(&h0);
                    u.y = *reinterpret_cast<unsigned*>(&h1);
                    *(uint2*)&dst[(size_t)gr * DIM + cb0 + lane * 4] = u;
                }
            } else {                                     // V transposed: vt[b][d][i]
                const int d0 = bn - 2 * DIM;
                const int b  = bm >> 11;                 // tile never straddles batches
                const int i0 = (bm & (SEQ - 1)) + h * 64;
#pragma unroll
                for (int dd = 0; dd < 16; dd++) {
                    const int d = dd * 8 + wid;
                    const float f0 = smf[(lane * 2) * EPI_PITCH + d];
                    const float f1 = smf[(lane * 2 + 1) * EPI_PITCH + d];
                    __half2 hv = __floats2half2_rn(f0, f1);
                    *(__half2*)&p.vt[((size_t)b * DIM + d0 + d) * SEQ + i0 + lane * 2] = hv;
                }
            }
        }
        __syncthreads();
    }
}

// ---------------- prep: x -> fp16 hi/lo split ----------------
__global__ void convert_x_kernel(const float* __restrict__ x,
                                 __half* __restrict__ xh, __half* __restrict__ xl) {
    size_t i = (size_t)blockIdx.x * blockDim.x + threadIdx.x;
    float4 v = ((const float4*)x)[i];
    __half h0 = __float2half(v.x), h1 = __float2half(v.y);
    __half h2 = __float2half(v.z), h3 = __float2half(v.w);
    ((__half2*)xh)[2 * i]     = __halves2half2(h0, h1);
    ((__half2*)xh)[2 * i + 1] = __halves2half2(h2, h3);
    __half l0 = __float2half(v.x - __half2float(h0));
    __half l1 = __float2half(v.y - __half2float(h1));
    __half l2 = __float2half(v.z - __half2float(h2));
    __half l3 = __float2half(v.w - __half2float(h3));
    ((__half2*)xl)[2 * i]     = __halves2half2(l0, l1);
    ((__half2*)xl)[2 * i + 1] = __halves2half2(l2, l3);
}

// ---------------- prep: w[k][n] -> Wt[n][k] fp16 (tiled transpose) ----------------
__global__ void prep_w_kernel(const float* __restrict__ w, __half* __restrict__ wh) {
    __shared__ float t[32][33];
    const int k0 = blockIdx.y * 32, n0 = blockIdx.x * 32;
#pragma unroll
    for (int r = 0; r < 32; r += 8)
        t[threadIdx.y + r][threadIdx.x] =
            w[(size_t)(k0 + threadIdx.y + r) * DIM + n0 + threadIdx.x];
    __syncthreads();
#pragma unroll
    for (int r = 0; r < 32; r += 8) {
        const int n = n0 + threadIdx.y + r;
        const int k = k0 + threadIdx.x;
        wh[(size_t)n * DIM + k] = __float2half(t[threadIdx.x][threadIdx.y + r]);
    }
}

// ---------------- softmax: rows of 2048, fp32 in -> fp16 probs ----------------
__global__ __launch_bounds__(256) void softmax_kernel(const float* __restrict__ S,
                                                      __half* __restrict__ P) {
    __shared__ float red[8];
    const size_t row = blockIdx.x;
    const float* sr = S + row * SEQ;
    __half* pr = P + row * SEQ;
    const int tid = threadIdx.x;

    float v[8];
    float m = -1e30f;
#pragma unroll
    for (int j = 0; j < 8; j++) { v[j] = sr[tid + j * 256]; m = fmaxf(m, v[j]); }
#pragma unroll
    for (int o = 16; o > 0; o >>= 1) m = fmaxf(m, __shfl_xor_sync(0xffffffffu, m, o));
    if ((tid & 31) == 0) red[tid >> 5] = m;
    __syncthreads();
    float M = red[0];
#pragma unroll
    for (int wv = 1; wv < 8; wv++) M = fmaxf(M, red[wv]);
    __syncthreads();

    float sum = 0.0f;
#pragma unroll
    for (int j = 0; j < 8; j++) { v[j] = __expf(v[j] - M); sum += v[j]; }
#pragma unroll
    for (int o = 16; o > 0; o >>= 1) sum += __shfl_xor_sync(0xffffffffu, sum, o);
    if ((tid & 31) == 0) red[tid >> 5] = sum;
    __syncthreads();
    float tot = 0.0f;
#pragma unroll
    for (int wv = 0; wv < 8; wv++) tot += red[wv];
    const float inv = 1.0f / tot;
#pragma unroll
    for (int j = 0; j < 8; j++) pr[tid + j * 256] = __float2half(v[j] * inv);
}

// ---------------- launch ----------------
extern "C" void kernel_launch(void* const* d_in, const int* in_sizes, int n_in,
                              void* d_out, int out_size) {
    const float* x = (const float*)d_in[0];
    const float* w[3] = { (const float*)d_in[1], (const float*)d_in[2], (const float*)d_in[3] };
    float* out = (float*)d_out;

    void *xh, *xl, *wth, *q, *k, *vt, *s, *pbuf;
    cudaGetSymbolAddress(&xh, g_xh);
    cudaGetSymbolAddress(&xl, g_xl);
    cudaGetSymbolAddress(&wth, g_wth);
    cudaGetSymbolAddress(&q, g_q);
    cudaGetSymbolAddress(&k, g_k);
    cudaGetSymbolAddress(&vt, g_vt);
    cudaGetSymbolAddress(&s, g_s);
    cudaGetSymbolAddress(&pbuf, g_p);

    cudaFuncSetAttribute(gemm_kernel<0, true>,
                         cudaFuncAttributeMaxDynamicSharedMemorySize, SM_SPLIT);
    cudaFuncSetAttribute(gemm_kernel<1, false>,
                         cudaFuncAttributeMaxDynamicSharedMemorySize, SM_PLAIN);
    cudaFuncSetAttribute(gemm_kernel<2, false>,
                         cudaFuncAttributeMaxDynamicSharedMemorySize, SM_PLAIN);

    // 1) input split to fp16 hi/lo
    convert_x_kernel<<<(MTOK * DIM / 4) / 256, 256>>>(x, (__half*)xh, (__half*)xl);

    // 2) weight transpose to fp16 Wt[3072][1024]
    for (int i = 0; i < 3; i++)
        prep_w_kernel<<<dim3(32, 32), dim3(32, 8)>>>(
            w[i], (__half*)wth + (size_t)i * DIM * DIM);

    // 3) fused QKV projection: (xh + xl) * Wh  -> Q/K fp16 + V^T fp16
    {
        GemmP p{};
        p.A = (__half*)xh;  p.Al = (__half*)xl;
        p.B = (__half*)wth;
        p.q = (__half*)q; p.k = (__half*)k; p.vt = (__half*)vt;
        p.lda = DIM; p.ldb = DIM; p.K = DIM; p.scale = 1.0f;
        gemm_kernel<0, true><<<dim3(3 * DIM / BN, MTOK / BM, 1), 256, SM_SPLIT>>>(p);
    }

    // 4) scores = Q K^T / 32 (per batch)
    {
        GemmP p{};
        p.A = (__half*)q; p.B = (__half*)k; p.C = (float*)s;
        p.sAz = (long long)SEQ * DIM; p.sBz = (long long)SEQ * DIM;
        p.sCz = (long long)SEQ * SEQ;
        p.lda = DIM; p.ldb = DIM; p.ldc = SEQ; p.K = DIM;
        p.scale = 1.0f / 32.0f;
        gemm_kernel<1, false><<<dim3(SEQ / BN, SEQ / BM, BATCH), 256, SM_PLAIN>>>(p);
    }

    // 5) softmax rows -> fp16 P
    softmax_kernel<<<BATCH * SEQ, 256>>>((const float*)s, (__half*)pbuf);

    // 6) out = P V (per batch)
    {
        GemmP p{};
        p.A = (__half*)pbuf; p.B = (__half*)vt; p.C = out;
        p.sAz = (long long)SEQ * SEQ; p.sBz = (long long)DIM * SEQ;
        p.sCz = (long long)SEQ * DIM;
        p.lda = SEQ; p.ldb = SEQ; p.ldc = DIM; p.K = SEQ;
        p.scale = 1.0f;
        gemm_kernel<2, false><<<dim3(DIM / BN, SEQ / BM, BATCH), 256, SM_PLAIN>>>(p);
    }
}

// round 11
// speedup vs baseline: 1.6928x; 1.2018x over previous
#include <cuda_runtime.h>
#include <cuda_fp16.h>

#define DEV_INLINE __device__ __forceinline__

// ---------------- problem constants ----------------
constexpr int BATCH = 4;
constexpr int SEQ   = 2048;
constexpr int DIM   = 1024;            // D == DQKV
constexpr int MTOK  = BATCH * SEQ;     // 8192

// ---------------- GEMM tiling (R2-proven config) ----------------
constexpr int BM = 128, BN = 128, BK = 32, SPAD = 8;
constexpr int LDS = BK + SPAD;                 // 40 halfs per smem row
constexpr int TILE_E = BM * LDS;               // 5120 elems per operand tile
constexpr int WM = 64, WN = 32;                // warp tile (8 warps: 2 x 4)
constexpr int EPI_PITCH = 132;                 // fp32 words per staged row
constexpr int EPI_BYTES = 64 * EPI_PITCH * 4;  // 33792 (one 64-row half)
constexpr int SM_PLAIN = 2 * 2 * TILE_E * 2;   // 40960 B (A,B x 2 stages)
constexpr int SM_SPLIT = 2 * 3 * TILE_E * 2;   // 61440 B (Ah,Al,B x 2 stages)
static_assert(EPI_BYTES <= SM_PLAIN, "epilogue staging fits");

// ---------------- scratch (static device allocations; no cudaMalloc) ----------------
__device__ __align__(16) __half g_xh[MTOK * DIM];
__device__ __align__(16) __half g_xl[MTOK * DIM];
__device__ __align__(16) __half g_wth[3 * DIM * DIM];        // Wt[n][k] fp16
__device__ __align__(16) __half g_q[MTOK * DIM];
__device__ __align__(16) __half g_k[MTOK * DIM];
__device__ __align__(16) __half g_vt[BATCH * DIM * SEQ];     // V^T [b][d][i]
__device__ __align__(16) float  g_s[(size_t)BATCH * SEQ * SEQ];
__device__ __align__(16) __half g_p[(size_t)BATCH * SEQ * SEQ];

// ---------------- PTX helpers ----------------
DEV_INLINE void cp16(unsigned dst, const void* src) {
    asm volatile("cp.async.cg.shared.global [%0], [%1], 16;\n" :: "r"(dst), "l"(src));
}
DEV_INLINE void cp_commit() { asm volatile("cp.async.commit_group;\n" ::: "memory"); }
template <int N> DEV_INLINE void cp_wait() {
    asm volatile("cp.async.wait_group %0;\n" :: "n"(N) : "memory");
}
DEV_INLINE void ldsm4(unsigned addr, unsigned& r0, unsigned& r1, unsigned& r2, unsigned& r3) {
    asm volatile("ldmatrix.sync.aligned.m8n8.x4.shared.b16 {%0,%1,%2,%3}, [%4];\n"
        : "=r"(r0), "=r"(r1), "=r"(r2), "=r"(r3) : "r"(addr));
}
DEV_INLINE void ldsm2(unsigned addr, unsigned& r0, unsigned& r1) {
    asm volatile("ldmatrix.sync.aligned.m8n8.x2.shared.b16 {%0,%1}, [%2];\n"
        : "=r"(r0), "=r"(r1) : "r"(addr));
}
DEV_INLINE void mma16816(float c[4], const unsigned a[4], const unsigned b[2]) {
    asm volatile(
        "mma.sync.aligned.m16n8k16.row.col.f32.f16.f16.f32 "
        "{%0,%1,%2,%3}, {%4,%5,%6,%7}, {%8,%9}, {%0,%1,%2,%3};\n"
        : "+f"(c[0]), "+f"(c[1]), "+f"(c[2]), "+f"(c[3])
        : "r"(a[0]), "r"(a[1]), "r"(a[2]), "r"(a[3]), "r"(b[0]), "r"(b[1]));
}

// ---------------- GEMM parameter block ----------------
struct GemmP {
    const __half* A;  const __half* Al;     // Al used only when SPLIT
    const __half* B;
    float* C;
    __half* q; __half* k; __half* vt;
    long long sAz, sBz, sCz;                // per-batch (blockIdx.z) element strides
    int lda, ldb, ldc, K;
    float scale;
};

// MODE 0: QKV projection epilogue (fp16 Q/K row-major + V transposed)
// MODE 1: scores epilogue (fp32 * scale)
// MODE 2: output epilogue (fp32)
template <int MODE, bool SPLIT>
__global__ __launch_bounds__(256, 2) void gemm_kernel(GemmP p) {
    extern __shared__ char smraw[];
    const unsigned su = (unsigned)__cvta_generic_to_shared(smraw);
    constexpr int STAGE_B = (SPLIT ? 3 : 2) * TILE_E * 2;   // bytes per stage
    constexpr int BOFF = (SPLIT ? 2 : 1) * TILE_E * 2;      // B-tile byte offset in stage

    const int tid = threadIdx.x;
    const int lane = tid & 31, wid = tid >> 5;
    const int bm = blockIdx.y * BM;
    const int bn = blockIdx.x * BN;

    const __half* A  = p.A + (size_t)blockIdx.z * p.sAz;
    const __half* B  = p.B + (size_t)blockIdx.z * p.sBz;
    const __half* Al = SPLIT ? (p.Al + (size_t)blockIdx.z * p.sAz) : nullptr;

    // gmem->smem: 512 16B chunks per tile, 2 per thread
    const int r0 = tid >> 2,         c0 = (tid & 3) * 8;
    const int r1 = (tid + 256) >> 2, c1 = ((tid + 256) & 3) * 8;

    auto load_stage = [&](int st, int k0) {
        const unsigned uA = su + (unsigned)(st * STAGE_B);
        const unsigned uB = uA + (unsigned)BOFF;
        cp16(uA + (r0 * LDS + c0) * 2, A + (size_t)(bm + r0) * p.lda + k0 + c0);
        cp16(uA + (r1 * LDS + c1) * 2, A + (size_t)(bm + r1) * p.lda + k0 + c1);
        if (SPLIT) {
            const unsigned uAl = uA + (unsigned)(TILE_E * 2);
            cp16(uAl + (r0 * LDS + c0) * 2, Al + (size_t)(bm + r0) * p.lda + k0 + c0);
            cp16(uAl + (r1 * LDS + c1) * 2, Al + (size_t)(bm + r1) * p.lda + k0 + c1);
        }
        cp16(uB + (r0 * LDS + c0) * 2, B + (size_t)(bn + r0) * p.ldb + k0 + c0);
        cp16(uB + (r1 * LDS + c1) * 2, B + (size_t)(bn + r1) * p.ldb + k0 + c1);
    };

    const int wm0 = (wid & 1) * WM;     // 0 / 64
    const int wn0 = (wid >> 1) * WN;    // 0 / 32 / 64 / 96

    int aoff[4], boff[4];
#pragma unroll
    for (int mt = 0; mt < 4; mt++)
        aoff[mt] = (wm0 + mt * 16 + (lane & 15)) * LDS + ((lane >> 4) << 3);
#pragma unroll
    for (int nt = 0; nt < 4; nt++)
        boff[nt] = (wn0 + nt * 8 + (lane & 7)) * LDS + (((lane >> 3) & 1) << 3);

    float acc[4][4][4];
#pragma unroll
    for (int mt = 0; mt < 4; mt++)
#pragma unroll
        for (int nt = 0; nt < 4; nt++)
#pragma unroll
            for (int i = 0; i < 4; i++) acc[mt][nt][i] = 0.0f;

    const int KT = p.K / BK;
    load_stage(0, 0);
    cp_commit();

    for (int kt = 0; kt < KT; kt++) {
        if (kt + 1 < KT) {
            load_stage((kt + 1) & 1, (kt + 1) * BK);
            cp_commit();
            cp_wait<1>();
        } else {
            cp_wait<0>();
        }
        __syncthreads();

        const int st = kt & 1;
        const unsigned uA  = su + (unsigned)(st * STAGE_B);
        const unsigned uB  = uA + (unsigned)BOFF;
        const unsigned uAl = uA + (unsigned)(TILE_E * 2);

#pragma unroll
        for (int kk = 0; kk < BK; kk += 16) {
            unsigned af[4][4], afl[4][4], bf[4][2];
#pragma unroll
            for (int mt = 0; mt < 4; mt++)
                ldsm4(uA + (unsigned)((aoff[mt] + kk) * 2),
                      af[mt][0], af[mt][1], af[mt][2], af[mt][3]);
            if (SPLIT) {
#pragma unroll
                for (int mt = 0; mt < 4; mt++)
                    ldsm4(uAl + (unsigned)((aoff[mt] + kk) * 2),
                          afl[mt][0], afl[mt][1], afl[mt][2], afl[mt][3]);
            }
#pragma unroll
            for (int nt = 0; nt < 4; nt++)
                ldsm2(uB + (unsigned)((boff[nt] + kk) * 2), bf[nt][0], bf[nt][1]);
#pragma unroll
            for (int mt = 0; mt < 4; mt++) {
#pragma unroll
                for (int nt = 0; nt < 4; nt++) {
                    mma16816(acc[mt][nt], af[mt], bf[nt]);
                    if (SPLIT) mma16816(acc[mt][nt], afl[mt], bf[nt]);   // x_lo * w_hi
                }
            }
        }
        __syncthreads();
    }

    // ---------------- epilogue: stage 64x128 fp32 halves through smem ----------------
    float* smf = (float*)smraw;
    const int g = lane >> 2, tg = lane & 3;

#pragma unroll
    for (int h = 0; h < 2; h++) {
        if (wm0 == h * 64) {
#pragma unroll
            for (int mt = 0; mt < 4; mt++) {
#pragma unroll
                for (int nt = 0; nt < 4; nt++) {
                    const int rl = mt * 16 + g;
                    const int c  = wn0 + nt * 8 + tg * 2;
                    const float* a = acc[mt][nt];
                    smf[rl * EPI_PITCH + c]           = a[0];
                    smf[rl * EPI_PITCH + c + 1]       = a[1];
                    smf[(rl + 8) * EPI_PITCH + c]     = a[2];
                    smf[(rl + 8) * EPI_PITCH + c + 1] = a[3];
                }
            }
        }
        __syncthreads();

        if (MODE == 1 || MODE == 2) {
            float* C = p.C + (size_t)blockIdx.z * p.sCz;
#pragma unroll
            for (int it = 0; it < 8; it++) {
                const int row = it * 8 + wid;
                const int gr = bm + h * 64 + row;
                float4 v = *(float4*)&smf[row * EPI_PITCH + lane * 4];
                if (MODE == 1) { v.x *= p.scale; v.y *= p.scale; v.z *= p.scale; v.w *= p.scale; }
                *(float4*)&C[(size_t)gr * p.ldc + bn + lane * 4] = v;
            }
        } else {
            if (bn < 2 * DIM) {                          // Q or K (row-major fp16)
                __half* dst = (bn < DIM) ? p.q : p.k;
                const int cb0 = (bn < DIM) ? bn : bn - DIM;
#pragma unroll
                for (int it = 0; it < 8; it++) {
                    const int row = it * 8 + wid;
                    const int gr = bm + h * 64 + row;
                    float4 v = *(float4*)&smf[row * EPI_PITCH + lane * 4];
                    __half2 h0 = __floats2half2_rn(v.x, v.y);
                    __half2 h1 = __floats2half2_rn(v.z, v.w);
                    uint2 u;
                    u.x = *reinterpret_cast<unsigned*>(&h0);
                    u.y = *reinterpret_cast<unsigned*>(&h1);
                    *(uint2*)&dst[(size_t)gr * DIM + cb0 + lane * 4] = u;
                }
            } else {                                     // V transposed: vt[b][d][i]
                const int d0 = bn - 2 * DIM;
                const int b  = bm >> 11;                 // tile never straddles batches
                const int i0 = (bm & (SEQ - 1)) + h * 64;
#pragma unroll
                for (int dd = 0; dd < 16; dd++) {
                    const int d = dd * 8 + wid;
                    const float f0 = smf[(lane * 2) * EPI_PITCH + d];
                    const float f1 = smf[(lane * 2 + 1) * EPI_PITCH + d];
                    __half2 hv = __floats2half2_rn(f0, f1);
                    *(__half2*)&p.vt[((size_t)b * DIM + d0 + d) * SEQ + i0 + lane * 2] = hv;
                }
            }
        }
        __syncthreads();
    }
}

// ---------------- prep: x -> fp16 hi/lo split ----------------
__global__ void convert_x_kernel(const float* __restrict__ x,
                                 __half* __restrict__ xh, __half* __restrict__ xl) {
    size_t i = (size_t)blockIdx.x * blockDim.x + threadIdx.x;
    float4 v = ((const float4*)x)[i];
    __half h0 = __float2half(v.x), h1 = __float2half(v.y);
    __half h2 = __float2half(v.z), h3 = __float2half(v.w);
    ((__half2*)xh)[2 * i]     = __halves2half2(h0, h1);
    ((__half2*)xh)[2 * i + 1] = __halves2half2(h2, h3);
    __half l0 = __float2half(v.x - __half2float(h0));
    __half l1 = __float2half(v.y - __half2float(h1));
    __half l2 = __float2half(v.z - __half2float(h2));
    __half l3 = __float2half(v.w - __half2float(h3));
    ((__half2*)xl)[2 * i]     = __halves2half2(l0, l1);
    ((__half2*)xl)[2 * i + 1] = __halves2half2(l2, l3);
}

// ---------------- prep: w[k][n] -> Wt[n][k] fp16 (tiled transpose) ----------------
__global__ void prep_w_kernel(const float* __restrict__ w, __half* __restrict__ wh) {
    __shared__ float t[32][33];
    const int k0 = blockIdx.y * 32, n0 = blockIdx.x * 32;
#pragma unroll
    for (int r = 0; r < 32; r += 8)
        t[threadIdx.y + r][threadIdx.x] =
            w[(size_t)(k0 + threadIdx.y + r) * DIM + n0 + threadIdx.x];
    __syncthreads();
#pragma unroll
    for (int r = 0; r < 32; r += 8) {
        const int n = n0 + threadIdx.y + r;
        const int k = k0 + threadIdx.x;
        wh[(size_t)n * DIM + k] = __float2half(t[threadIdx.x][threadIdx.y + r]);
    }
}

// ---------------- softmax: rows of 2048, fp32 in -> fp16 probs ----------------
__global__ __launch_bounds__(256) void softmax_kernel(const float* __restrict__ S,
                                                      __half* __restrict__ P) {
    __shared__ float red[8];
    const size_t row = blockIdx.x;
    const float* sr = S + row * SEQ;
    __half* pr = P + row * SEQ;
    const int tid = threadIdx.x;

    float v[8];
    float m = -1e30f;
#pragma unroll
    for (int j = 0; j < 8; j++) { v[j] = sr[tid + j * 256]; m = fmaxf(m, v[j]); }
#pragma unroll
    for (int o = 16; o > 0; o >>= 1) m = fmaxf(m, __shfl_xor_sync(0xffffffffu, m, o));
    if ((tid & 31) == 0) red[tid >> 5] = m;
    __syncthreads();
    float M = red[0];
#pragma unroll
    for (int wv = 1; wv < 8; wv++) M = fmaxf(M, red[wv]);
    __syncthreads();

    float sum = 0.0f;
#pragma unroll
    for (int j = 0; j < 8; j++) { v[j] = __expf(v[j] - M); sum += v[j]; }
#pragma unroll
    for (int o = 16; o > 0; o >>= 1) sum += __shfl_xor_sync(0xffffffffu, sum, o);
    if ((tid & 31) == 0) red[tid >> 5] = sum;
    __syncthreads();
    float tot = 0.0f;
#pragma unroll
    for (int wv = 0; wv < 8; wv++) tot += red[wv];
    const float inv = 1.0f / tot;
#pragma unroll
    for (int j = 0; j < 8; j++) pr[tid + j * 256] = __float2half(v[j] * inv);
}

// ---------------- launch ----------------
extern "C" void kernel_launch(void* const* d_in, const int* in_sizes, int n_in,
                              void* d_out, int out_size) {
    const float* x = (const float*)d_in[0];
    const float* w[3] = { (const float*)d_in[1], (const float*)d_in[2], (const float*)d_in[3] };
    float* out = (float*)d_out;

    void *xh, *xl, *wth, *q, *k, *vt, *s, *pbuf;
    cudaGetSymbolAddress(&xh, g_xh);
    cudaGetSymbolAddress(&xl, g_xl);
    cudaGetSymbolAddress(&wth, g_wth);
    cudaGetSymbolAddress(&q, g_q);
    cudaGetSymbolAddress(&k, g_k);
    cudaGetSymbolAddress(&vt, g_vt);
    cudaGetSymbolAddress(&s, g_s);
    cudaGetSymbolAddress(&pbuf, g_p);

    cudaFuncSetAttribute(gemm_kernel<0, true>,
                         cudaFuncAttributeMaxDynamicSharedMemorySize, SM_SPLIT);
    cudaFuncSetAttribute(gemm_kernel<1, false>,
                         cudaFuncAttributeMaxDynamicSharedMemorySize, SM_PLAIN);
    cudaFuncSetAttribute(gemm_kernel<2, false>,
                         cudaFuncAttributeMaxDynamicSharedMemorySize, SM_PLAIN);

    // 1) input split to fp16 hi/lo
    convert_x_kernel<<<(MTOK * DIM / 4) / 256, 256>>>(x, (__half*)xh, (__half*)xl);

    // 2) weight transpose to fp16 Wt[3072][1024]
    for (int i = 0; i < 3; i++)
        prep_w_kernel<<<dim3(32, 32), dim3(32, 8)>>>(
            w[i], (__half*)wth + (size_t)i * DIM * DIM);

    // 3) fused QKV projection: (xh + xl) * Wh  -> Q/K fp16 + V^T fp16
    {
        GemmP p{};
        p.A = (__half*)xh;  p.Al = (__half*)xl;
        p.B = (__half*)wth;
        p.q = (__half*)q; p.k = (__half*)k; p.vt = (__half*)vt;
        p.lda = DIM; p.ldb = DIM; p.K = DIM; p.scale = 1.0f;
        gemm_kernel<0, true><<<dim3(3 * DIM / BN, MTOK / BM, 1), 256, SM_SPLIT>>>(p);
    }

    // 4) scores = Q K^T / 32 (per batch)
    {
        GemmP p{};
        p.A = (__half*)q; p.B = (__half*)k; p.C = (float*)s;
        p.sAz = (long long)SEQ * DIM; p.sBz = (long long)SEQ * DIM;
        p.sCz = (long long)SEQ * SEQ;
        p.lda = DIM; p.ldb = DIM; p.ldc = SEQ; p.K = DIM;
        p.scale = 1.0f / 32.0f;
        gemm_kernel<1, false><<<dim3(SEQ / BN, SEQ / BM, BATCH), 256, SM_PLAIN>>>(p);
    }

    // 5) softmax rows -> fp16 P
    softmax_kernel<<<BATCH * SEQ, 256>>>((const float*)s, (__half*)pbuf);

    // 6) out = P V (per batch)
    {
        GemmP p{};
        p.A = (__half*)pbuf; p.B = (__half*)vt; p.C = out;
        p.sAz = (long long)SEQ * SEQ; p.sBz = (long long)DIM * SEQ;
        p.sCz = (long long)SEQ * DIM;
        p.lda = SEQ; p.ldb = SEQ; p.ldc = DIM; p.K = SEQ;
        p.scale = 1.0f;
        gemm_kernel<2, false><<<dim3(DIM / BN, SEQ / BM, BATCH), 256, SM_PLAIN>>>(p);
    }
}

// round 14
// speedup vs baseline: 1.8860x; 1.1142x over previous
#include <cuda_runtime.h>
#include <cuda_fp16.h>

#define DEV_INLINE __device__ __forceinline__

// ---------------- problem constants ----------------
constexpr int BATCH = 4;
constexpr int SEQ   = 2048;
constexpr int DIM   = 1024;            // D == DQKV
constexpr int MTOK  = BATCH * SEQ;     // 8192

// ---------------- GEMM tiling: 128x128x32 block, 4 warps of 64x64 ----------------
constexpr int BM = 128, BN = 128, BK = 32, SPAD = 8;
constexpr int LDS = BK + SPAD;                 // 40 halfs per smem row
constexpr int TILE_E = BM * LDS;               // 5120 elems per operand tile
constexpr int EPI_PITCH = 132;                 // fp32 words per staged row
constexpr int EPI_BYTES = 64 * EPI_PITCH * 4;  // 33792 (one 64-row half)
constexpr int SM_PLAIN = 2 * 2 * TILE_E * 2;   // 40960 B (A,B x 2 stages)
constexpr int SM_SPLIT = 2 * 3 * TILE_E * 2;   // 61440 B (Ah,Al,B x 2 stages)
static_assert(EPI_BYTES <= SM_PLAIN, "epilogue staging fits");

// ---------------- scratch (static device allocations; no cudaMalloc) ----------------
__device__ __align__(16) __half g_xh[MTOK * DIM];
__device__ __align__(16) __half g_xl[MTOK * DIM];
__device__ __align__(16) __half g_wth[3 * DIM * DIM];        // Wt[n][k] fp16
__device__ __align__(16) __half g_q[MTOK * DIM];
__device__ __align__(16) __half g_k[MTOK * DIM];
__device__ __align__(16) __half g_vt[BATCH * DIM * SEQ];     // V^T [b][d][i]
__device__ __align__(16) float  g_s[(size_t)BATCH * SEQ * SEQ];
__device__ __align__(16) __half g_p[(size_t)BATCH * SEQ * SEQ];

// ---------------- PTX helpers ----------------
DEV_INLINE void cp16(unsigned dst, const void* src) {
    asm volatile("cp.async.cg.shared.global [%0], [%1], 16;\n" :: "r"(dst), "l"(src));
}
DEV_INLINE void cp_commit() { asm volatile("cp.async.commit_group;\n" ::: "memory"); }
template <int N> DEV_INLINE void cp_wait() {
    asm volatile("cp.async.wait_group %0;\n" :: "n"(N) : "memory");
}
DEV_INLINE void ldsm4(unsigned addr, unsigned& r0, unsigned& r1, unsigned& r2, unsigned& r3) {
    asm volatile("ldmatrix.sync.aligned.m8n8.x4.shared.b16 {%0,%1,%2,%3}, [%4];\n"
        : "=r"(r0), "=r"(r1), "=r"(r2), "=r"(r3) : "r"(addr));
}
DEV_INLINE void ldsm2(unsigned addr, unsigned& r0, unsigned& r1) {
    asm volatile("ldmatrix.sync.aligned.m8n8.x2.shared.b16 {%0,%1}, [%2];\n"
        : "=r"(r0), "=r"(r1) : "r"(addr));
}
DEV_INLINE void mma16816(float c[4], const unsigned a[4], const unsigned b[2]) {
    asm volatile(
        "mma.sync.aligned.m16n8k16.row.col.f32.f16.f16.f32 "
        "{%0,%1,%2,%3}, {%4,%5,%6,%7}, {%8,%9}, {%0,%1,%2,%3};\n"
        : "+f"(c[0]), "+f"(c[1]), "+f"(c[2]), "+f"(c[3])
        : "r"(a[0]), "r"(a[1]), "r"(a[2]), "r"(a[3]), "r"(b[0]), "r"(b[1]));
}

// ---------------- GEMM parameter block ----------------
struct GemmP {
    const __half* A;  const __half* Al;     // Al used only when SPLIT
    const __half* B;
    float* C;
    __half* q; __half* k; __half* vt;
    long long sAz, sBz, sCz;                // per-batch (blockIdx.z) element strides
    int lda, ldb, ldc, K;
    float scale;
};

// MODE 0: QKV projection epilogue (fp16 Q/K row-major + V transposed)
// MODE 1: scores epilogue (fp32 * scale)
// MODE 2: output epilogue (fp32)
template <int MODE, bool SPLIT>
__global__ __launch_bounds__(128, 2) void gemm_kernel(GemmP p) {
    extern __shared__ char smraw[];
    const unsigned su = (unsigned)__cvta_generic_to_shared(smraw);
    constexpr int STAGE_B = (SPLIT ? 3 : 2) * TILE_E * 2;   // bytes per stage
    constexpr int BOFF = (SPLIT ? 2 : 1) * TILE_E * 2;      // B-tile byte offset in stage

    const int tid = threadIdx.x;
    const int lane = tid & 31, wid = tid >> 5;              // 4 warps
    const int bm = blockIdx.y * BM;
    const int bn = blockIdx.x * BN;

    const __half* A  = p.A + (size_t)blockIdx.z * p.sAz;
    const __half* B  = p.B + (size_t)blockIdx.z * p.sBz;
    const __half* Al = SPLIT ? (p.Al + (size_t)blockIdx.z * p.sAz) : nullptr;

    // gmem->smem: 512 16B chunks per tile, 4 per thread (128 threads)
    auto load_tile = [&](const __half* G, int ld, int rbase, unsigned sbase, int k0) {
#pragma unroll
        for (int i = 0; i < 4; i++) {
            const int ch = tid + i * 128;                   // 0..511
            const int row = ch >> 2, cc = (ch & 3) * 8;
            cp16(sbase + (unsigned)((row * LDS + cc) * 2),
                 G + (size_t)(rbase + row) * ld + k0 + cc);
        }
    };
    auto load_stage = [&](int st, int k0) {
        const unsigned uA = su + (unsigned)(st * STAGE_B);
        load_tile(A, p.lda, bm, uA, k0);
        if (SPLIT) load_tile(Al, p.lda, bm, uA + (unsigned)(TILE_E * 2), k0);
        load_tile(B, p.ldb, bn, uA + (unsigned)BOFF, k0);
    };

    const int wm0 = (wid & 1) * 64;     // 0 / 64
    const int wn0 = (wid >> 1) * 64;    // 0 / 64

    int aoff[4], boff[8];
#pragma unroll
    for (int mt = 0; mt < 4; mt++)
        aoff[mt] = (wm0 + mt * 16 + (lane & 15)) * LDS + ((lane >> 4) << 3);
#pragma unroll
    for (int nt = 0; nt < 8; nt++)
        boff[nt] = (wn0 + nt * 8 + (lane & 7)) * LDS + (((lane >> 3) & 1) << 3);

    float acc[4][8][4];
#pragma unroll
    for (int mt = 0; mt < 4; mt++)
#pragma unroll
        for (int nt = 0; nt < 8; nt++)
#pragma unroll
            for (int i = 0; i < 4; i++) acc[mt][nt][i] = 0.0f;

    const int KT = p.K / BK;
    load_stage(0, 0);
    cp_commit();

    for (int kt = 0; kt < KT; kt++) {
        if (kt + 1 < KT) {
            load_stage((kt + 1) & 1, (kt + 1) * BK);
            cp_commit();
            cp_wait<1>();
        } else {
            cp_wait<0>();
        }
        __syncthreads();

        const int st = kt & 1;
        const unsigned uA  = su + (unsigned)(st * STAGE_B);
        const unsigned uB  = uA + (unsigned)BOFF;
        const unsigned uAl = uA + (unsigned)(TILE_E * 2);

#pragma unroll
        for (int kk = 0; kk < BK; kk += 16) {
            unsigned af[4][4], afl[4][4], bf[8][2];
#pragma unroll
            for (int mt = 0; mt < 4; mt++)
                ldsm4(uA + (unsigned)((aoff[mt] + kk) * 2),
                      af[mt][0], af[mt][1], af[mt][2], af[mt][3]);
            if (SPLIT) {
#pragma unroll
                for (int mt = 0; mt < 4; mt++)
                    ldsm4(uAl + (unsigned)((aoff[mt] + kk) * 2),
                          afl[mt][0], afl[mt][1], afl[mt][2], afl[mt][3]);
            }
#pragma unroll
            for (int nt = 0; nt < 8; nt++)
                ldsm2(uB + (unsigned)((boff[nt] + kk) * 2), bf[nt][0], bf[nt][1]);
#pragma unroll
            for (int mt = 0; mt < 4; mt++) {
#pragma unroll
                for (int nt = 0; nt < 8; nt++) {
                    mma16816(acc[mt][nt], af[mt], bf[nt]);
                    if (SPLIT) mma16816(acc[mt][nt], afl[mt], bf[nt]);   // x_lo * w_hi
                }
            }
        }
        __syncthreads();
    }

    // ---------------- epilogue: stage 64x128 fp32 halves through smem ----------------
    float* smf = (float*)smraw;
    const int g = lane >> 2, tg = lane & 3;

#pragma unroll
    for (int h = 0; h < 2; h++) {
        if (wm0 == h * 64) {                // 2 warps per half (wid 0,2 / 1,3)
#pragma unroll
            for (int mt = 0; mt < 4; mt++) {
#pragma unroll
                for (int nt = 0; nt < 8; nt++) {
                    const int rl = mt * 16 + g;
                    const int c  = wn0 + nt * 8 + tg * 2;
                    const float* a = acc[mt][nt];
                    smf[rl * EPI_PITCH + c]           = a[0];
                    smf[rl * EPI_PITCH + c + 1]       = a[1];
                    smf[(rl + 8) * EPI_PITCH + c]     = a[2];
                    smf[(rl + 8) * EPI_PITCH + c + 1] = a[3];
                }
            }
        }
        __syncthreads();

        if (MODE == 1 || MODE == 2) {
            float* C = p.C + (size_t)blockIdx.z * p.sCz;
#pragma unroll
            for (int it = 0; it < 16; it++) {
                const int row = it * 4 + wid;
                const int gr = bm + h * 64 + row;
                float4 v = *(float4*)&smf[row * EPI_PITCH + lane * 4];
                if (MODE == 1) { v.x *= p.scale; v.y *= p.scale; v.z *= p.scale; v.w *= p.scale; }
                *(float4*)&C[(size_t)gr * p.ldc + bn + lane * 4] = v;
            }
        } else {
            if (bn < 2 * DIM) {                          // Q or K (row-major fp16)
                __half* dst = (bn < DIM) ? p.q : p.k;
                const int cb0 = (bn < DIM) ? bn : bn - DIM;
#pragma unroll
                for (int it = 0; it < 16; it++) {
                    const int row = it * 4 + wid;
                    const int gr = bm + h * 64 + row;
                    float4 v = *(float4*)&smf[row * EPI_PITCH + lane * 4];
                    __half2 h0 = __floats2half2_rn(v.x, v.y);
                    __half2 h1 = __floats2half2_rn(v.z, v.w);
                    uint2 u;
                    u.x = *reinterpret_cast<unsigned*>(&h0);
                    u.y = *reinterpret_cast<unsigned*>(&h1);
                    *(uint2*)&dst[(size_t)gr * DIM + cb0 + lane * 4] = u;
                }
            } else {                                     // V transposed: vt[b][d][i]
                const int d0 = bn - 2 * DIM;
                const int b  = bm >> 11;                 // tile never straddles batches
                const int i0 = (bm & (SEQ - 1)) + h * 64;
#pragma unroll
                for (int dd = 0; dd < 32; dd++) {
                    const int d = dd * 4 + wid;
                    const float f0 = smf[(lane * 2) * EPI_PITCH + d];
                    const float f1 = smf[(lane * 2 + 1) * EPI_PITCH + d];
                    __half2 hv = __floats2half2_rn(f0, f1);
                    *(__half2*)&p.vt[((size_t)b * DIM + d0 + d) * SEQ + i0 + lane * 2] = hv;
                }
            }
        }
        __syncthreads();
    }
}

// ---------------- prep: x -> fp16 hi/lo split ----------------
__global__ void convert_x_kernel(const float* __restrict__ x,
                                 __half* __restrict__ xh, __half* __restrict__ xl) {
    size_t i = (size_t)blockIdx.x * blockDim.x + threadIdx.x;
    float4 v = ((const float4*)x)[i];
    __half h0 = __float2half(v.x), h1 = __float2half(v.y);
    __half h2 = __float2half(v.z), h3 = __float2half(v.w);
    ((__half2*)xh)[2 * i]     = __halves2half2(h0, h1);
    ((__half2*)xh)[2 * i + 1] = __halves2half2(h2, h3);
    __half l0 = __float2half(v.x - __half2float(h0));
    __half l1 = __float2half(v.y - __half2float(h1));
    __half l2 = __float2half(v.z - __half2float(h2));
    __half l3 = __float2half(v.w - __half2float(h3));
    ((__half2*)xl)[2 * i]     = __halves2half2(l0, l1);
    ((__half2*)xl)[2 * i + 1] = __halves2half2(l2, l3);
}

// ---------------- prep: w[k][n] -> Wt[n][k] fp16 (tiled transpose) ----------------
__global__ void prep_w_kernel(const float* __restrict__ w, __half* __restrict__ wh) {
    __shared__ float t[32][33];
    const int k0 = blockIdx.y * 32, n0 = blockIdx.x * 32;
#pragma unroll
    for (int r = 0; r < 32; r += 8)
        t[threadIdx.y + r][threadIdx.x] =
            w[(size_t)(k0 + threadIdx.y + r) * DIM + n0 + threadIdx.x];
    __syncthreads();
#pragma unroll
    for (int r = 0; r < 32; r += 8) {
        const int n = n0 + threadIdx.y + r;
        const int k = k0 + threadIdx.x;
        wh[(size_t)n * DIM + k] = __float2half(t[threadIdx.x][threadIdx.y + r]);
    }
}

// ---------------- softmax: rows of 2048, fp32 in -> fp16 probs ----------------
__global__ __launch_bounds__(256) void softmax_kernel(const float* __restrict__ S,
                                                      __half* __restrict__ P) {
    __shared__ float red[8];
    const size_t row = blockIdx.x;
    const float* sr = S + row * SEQ;
    __half* pr = P + row * SEQ;
    const int tid = threadIdx.x;

    float v[8];
    float m = -1e30f;
#pragma unroll
    for (int j = 0; j < 8; j++) { v[j] = sr[tid + j * 256]; m = fmaxf(m, v[j]); }
#pragma unroll
    for (int o = 16; o > 0; o >>= 1) m = fmaxf(m, __shfl_xor_sync(0xffffffffu, m, o));
    if ((tid & 31) == 0) red[tid >> 5] = m;
    __syncthreads();
    float M = red[0];
#pragma unroll
    for (int wv = 1; wv < 8; wv++) M = fmaxf(M, red[wv]);
    __syncthreads();

    float sum = 0.0f;
#pragma unroll
    for (int j = 0; j < 8; j++) { v[j] = __expf(v[j] - M); sum += v[j]; }
#pragma unroll
    for (int o = 16; o > 0; o >>= 1) sum += __shfl_xor_sync(0xffffffffu, sum, o);
    if ((tid & 31) == 0) red[tid >> 5] = sum;
    __syncthreads();
    float tot = 0.0f;
#pragma unroll
    for (int wv = 0; wv < 8; wv++) tot += red[wv];
    const float inv = 1.0f / tot;
#pragma unroll
    for (int j = 0; j < 8; j++) pr[tid + j * 256] = __float2half(v[j] * inv);
}

// ---------------- launch ----------------
extern "C" void kernel_launch(void* const* d_in, const int* in_sizes, int n_in,
                              void* d_out, int out_size) {
    const float* x = (const float*)d_in[0];
    const float* w[3] = { (const float*)d_in[1], (const float*)d_in[2], (const float*)d_in[3] };
    float* out = (float*)d_out;

    void *xh, *xl, *wth, *q, *k, *vt, *s, *pbuf;
    cudaGetSymbolAddress(&xh, g_xh);
    cudaGetSymbolAddress(&xl, g_xl);
    cudaGetSymbolAddress(&wth, g_wth);
    cudaGetSymbolAddress(&q, g_q);
    cudaGetSymbolAddress(&k, g_k);
    cudaGetSymbolAddress(&vt, g_vt);
    cudaGetSymbolAddress(&s, g_s);
    cudaGetSymbolAddress(&pbuf, g_p);

    cudaFuncSetAttribute(gemm_kernel<0, true>,
                         cudaFuncAttributeMaxDynamicSharedMemorySize, SM_SPLIT);
    cudaFuncSetAttribute(gemm_kernel<1, false>,
                         cudaFuncAttributeMaxDynamicSharedMemorySize, SM_PLAIN);
    cudaFuncSetAttribute(gemm_kernel<2, false>,
                         cudaFuncAttributeMaxDynamicSharedMemorySize, SM_PLAIN);

    // 1) input split to fp16 hi/lo
    convert_x_kernel<<<(MTOK * DIM / 4) / 256, 256>>>(x, (__half*)xh, (__half*)xl);

    // 2) weight transpose to fp16 Wt[3072][1024]
    for (int i = 0; i < 3; i++)
        prep_w_kernel<<<dim3(32, 32), dim3(32, 8)>>>(
            w[i], (__half*)wth + (size_t)i * DIM * DIM);

    // 3) fused QKV projection: (xh + xl) * Wh  -> Q/K fp16 + V^T fp16
    {
        GemmP p{};
        p.A = (__half*)xh;  p.Al = (__half*)xl;
        p.B = (__half*)wth;
        p.q = (__half*)q; p.k = (__half*)k; p.vt = (__half*)vt;
        p.lda = DIM; p.ldb = DIM; p.K = DIM; p.scale = 1.0f;
        gemm_kernel<0, true><<<dim3(3 * DIM / BN, MTOK / BM, 1), 128, SM_SPLIT>>>(p);
    }

    // 4) scores = Q K^T / 32 (per batch)
    {
        GemmP p{};
        p.A = (__half*)q; p.B = (__half*)k; p.C = (float*)s;
        p.sAz = (long long)SEQ * DIM; p.sBz = (long long)SEQ * DIM;
        p.sCz = (long long)SEQ * SEQ;
        p.lda = DIM; p.ldb = DIM; p.ldc = SEQ; p.K = DIM;
        p.scale = 1.0f / 32.0f;
        gemm_kernel<1, false><<<dim3(SEQ / BN, SEQ / BM, BATCH), 128, SM_PLAIN>>>(p);
    }

    // 5) softmax rows -> fp16 P
    softmax_kernel<<<BATCH * SEQ, 256>>>((const float*)s, (__half*)pbuf);

    // 6) out = P V (per batch)
    {
        GemmP p{};
        p.A = (__half*)pbuf; p.B = (__half*)vt; p.C = out;
        p.sAz = (long long)SEQ * SEQ; p.sBz = (long long)DIM * SEQ;
        p.sCz = (long long)SEQ * DIM;
        p.lda = SEQ; p.ldb = SEQ; p.ldc = DIM; p.K = SEQ;
        p.scale = 1.0f;
        gemm_kernel<2, false><<<dim3(DIM / BN, SEQ / BM, BATCH), 128, SM_PLAIN>>>(p);
    }
}

// round 15
// speedup vs baseline: 1.9070x; 1.0111x over previous
#include <cuda_runtime.h>
#include <cuda_fp16.h>

#define DEV_INLINE __device__ __forceinline__

// ---------------- problem constants ----------------
constexpr int BATCH = 4;
constexpr int SEQ   = 2048;
constexpr int DIM   = 1024;            // D == DQKV
constexpr int MTOK  = BATCH * SEQ;     // 8192

// ---------------- GEMM tiling: 128x128x64 block, 4 warps of 64x64 ----------------
constexpr int BM = 128, BN = 128, BK = 64, SPAD = 8;
constexpr int LDS = BK + SPAD;                 // 72 halfs per smem row
constexpr int TILE_E = BM * LDS;               // 9216 elems per operand tile
constexpr int EPI_PITCH = 132;                 // fp32 words per staged row
constexpr int EPI_BYTES = 64 * EPI_PITCH * 4;  // 33792 (one 64-row half)
constexpr int SM_PLAIN = 2 * 2 * TILE_E * 2;   //  73728 B (A,B x 2 stages)
constexpr int SM_SPLIT = 2 * 3 * TILE_E * 2;   // 110592 B (Ah,Al,B x 2 stages)
static_assert(EPI_BYTES <= SM_PLAIN, "epilogue staging fits");

// ---------------- scratch (static device allocations; no cudaMalloc) ----------------
__device__ __align__(16) __half g_xh[MTOK * DIM];
__device__ __align__(16) __half g_xl[MTOK * DIM];
__device__ __align__(16) __half g_wth[3 * DIM * DIM];        // Wt[n][k] fp16
__device__ __align__(16) __half g_q[MTOK * DIM];
__device__ __align__(16) __half g_k[MTOK * DIM];
__device__ __align__(16) __half g_vt[BATCH * DIM * SEQ];     // V^T [b][d][i]
__device__ __align__(16) float  g_s[(size_t)BATCH * SEQ * SEQ];
__device__ __align__(16) __half g_p[(size_t)BATCH * SEQ * SEQ];

// ---------------- PTX helpers ----------------
DEV_INLINE void cp16(unsigned dst, const void* src) {
    asm volatile("cp.async.cg.shared.global [%0], [%1], 16;\n" :: "r"(dst), "l"(src));
}
DEV_INLINE void cp_commit() { asm volatile("cp.async.commit_group;\n" ::: "memory"); }
template <int N> DEV_INLINE void cp_wait() {
    asm volatile("cp.async.wait_group %0;\n" :: "n"(N) : "memory");
}
DEV_INLINE void ldsm4(unsigned addr, unsigned& r0, unsigned& r1, unsigned& r2, unsigned& r3) {
    asm volatile("ldmatrix.sync.aligned.m8n8.x4.shared.b16 {%0,%1,%2,%3}, [%4];\n"
        : "=r"(r0), "=r"(r1), "=r"(r2), "=r"(r3) : "r"(addr));
}
DEV_INLINE void mma16816(float c[4], const unsigned a[4], const unsigned b[2]) {
    asm volatile(
        "mma.sync.aligned.m16n8k16.row.col.f32.f16.f16.f32 "
        "{%0,%1,%2,%3}, {%4,%5,%6,%7}, {%8,%9}, {%0,%1,%2,%3};\n"
        : "+f"(c[0]), "+f"(c[1]), "+f"(c[2]), "+f"(c[3])
        : "r"(a[0]), "r"(a[1]), "r"(a[2]), "r"(a[3]), "r"(b[0]), "r"(b[1]));
}

// ---------------- GEMM parameter block ----------------
struct GemmP {
    const __half* A;  const __half* Al;     // Al used only when SPLIT
    const __half* B;
    float* C;
    __half* q; __half* k; __half* vt;
    long long sAz, sBz, sCz;                // per-batch (blockIdx.z) element strides
    int lda, ldb, ldc, K;
    float scale;
};

// MODE 0: QKV projection epilogue (fp16 Q/K row-major + V transposed)
// MODE 1: scores epilogue (fp32 * scale)
// MODE 2: output epilogue (fp32)
template <int MODE, bool SPLIT>
__global__ __launch_bounds__(128, 2) void gemm_kernel(GemmP p) {
    extern __shared__ char smraw[];
    const unsigned su = (unsigned)__cvta_generic_to_shared(smraw);
    constexpr int STAGE_B = (SPLIT ? 3 : 2) * TILE_E * 2;   // bytes per stage
    constexpr int BOFF = (SPLIT ? 2 : 1) * TILE_E * 2;      // B-tile byte offset in stage

    const int tid = threadIdx.x;
    const int lane = tid & 31, wid = tid >> 5;              // 4 warps
    const int bm = blockIdx.y * BM;
    const int bn = blockIdx.x * BN;

    const __half* A  = p.A + (size_t)blockIdx.z * p.sAz;
    const __half* B  = p.B + (size_t)blockIdx.z * p.sBz;
    const __half* Al = SPLIT ? (p.Al + (size_t)blockIdx.z * p.sAz) : nullptr;

    // gmem->smem: 128x64 halves per tile = 1024 16B chunks, 8 per thread
    auto load_tile = [&](const __half* G, int ld, int rbase, unsigned sbase, int k0) {
#pragma unroll
        for (int i = 0; i < 8; i++) {
            const int ch = tid + i * 128;                   // 0..1023
            const int row = ch >> 3, cc = (ch & 7) * 8;
            cp16(sbase + (unsigned)((row * LDS + cc) * 2),
                 G + (size_t)(rbase + row) * ld + k0 + cc);
        }
    };
    auto load_stage = [&](int st, int k0) {
        const unsigned uA = su + (unsigned)(st * STAGE_B);
        load_tile(A, p.lda, bm, uA, k0);
        if (SPLIT) load_tile(Al, p.lda, bm, uA + (unsigned)(TILE_E * 2), k0);
        load_tile(B, p.ldb, bn, uA + (unsigned)BOFF, k0);
    };

    const int wm0 = (wid & 1) * 64;     // 0 / 64
    const int wn0 = (wid >> 1) * 64;    // 0 / 64

    // A fragments: ldsm4 per m16 tile (4 tiles)
    int aoff[4];
#pragma unroll
    for (int mt = 0; mt < 4; mt++)
        aoff[mt] = (wm0 + mt * 16 + (lane & 15)) * LDS + ((lane >> 4) << 3);
    // B fragments: ldsm4 per n16 pair (4 pairs -> 8 n8 tiles)
    int boff[4];
#pragma unroll
    for (int np = 0; np < 4; np++)
        boff[np] = (wn0 + np * 16 + ((lane >> 4) << 3) + (lane & 7)) * LDS
                 + (((lane >> 3) & 1) << 3);

    float acc[4][8][4];
#pragma unroll
    for (int mt = 0; mt < 4; mt++)
#pragma unroll
        for (int nt = 0; nt < 8; nt++)
#pragma unroll
            for (int i = 0; i < 4; i++) acc[mt][nt][i] = 0.0f;

    const int KT = p.K / BK;
    load_stage(0, 0);
    cp_commit();

    for (int kt = 0; kt < KT; kt++) {
        if (kt + 1 < KT) {
            load_stage((kt + 1) & 1, (kt + 1) * BK);
            cp_commit();
            cp_wait<1>();
        } else {
            cp_wait<0>();
        }
        __syncthreads();

        const int st = kt & 1;
        const unsigned uA  = su + (unsigned)(st * STAGE_B);
        const unsigned uB  = uA + (unsigned)BOFF;
        const unsigned uAl = uA + (unsigned)(TILE_E * 2);

#pragma unroll
        for (int kk = 0; kk < BK; kk += 16) {
            unsigned af[4][4], afl[4][4], bf[8][2];
#pragma unroll
            for (int mt = 0; mt < 4; mt++)
                ldsm4(uA + (unsigned)((aoff[mt] + kk) * 2),
                      af[mt][0], af[mt][1], af[mt][2], af[mt][3]);
            if (SPLIT) {
#pragma unroll
                for (int mt = 0; mt < 4; mt++)
                    ldsm4(uAl + (unsigned)((aoff[mt] + kk) * 2),
                          afl[mt][0], afl[mt][1], afl[mt][2], afl[mt][3]);
            }
#pragma unroll
            for (int np = 0; np < 4; np++)
                ldsm4(uB + (unsigned)((boff[np] + kk) * 2),
                      bf[np * 2][0], bf[np * 2][1], bf[np * 2 + 1][0], bf[np * 2 + 1][1]);
#pragma unroll
            for (int mt = 0; mt < 4; mt++) {
#pragma unroll
                for (int nt = 0; nt < 8; nt++) {
                    mma16816(acc[mt][nt], af[mt], bf[nt]);
                    if (SPLIT) mma16816(acc[mt][nt], afl[mt], bf[nt]);   // x_lo * w_hi
                }
            }
        }
        __syncthreads();
    }

    // ---------------- epilogue: stage 64x128 fp32 halves through smem ----------------
    float* smf = (float*)smraw;
    const int g = lane >> 2, tg = lane & 3;

#pragma unroll
    for (int h = 0; h < 2; h++) {
        if (wm0 == h * 64) {                // 2 warps per half (wid 0,2 / 1,3)
#pragma unroll
            for (int mt = 0; mt < 4; mt++) {
#pragma unroll
                for (int nt = 0; nt < 8; nt++) {
                    const int rl = mt * 16 + g;
                    const int c  = wn0 + nt * 8 + tg * 2;
                    const float* a = acc[mt][nt];
                    smf[rl * EPI_PITCH + c]           = a[0];
                    smf[rl * EPI_PITCH + c + 1]       = a[1];
                    smf[(rl + 8) * EPI_PITCH + c]     = a[2];
                    smf[(rl + 8) * EPI_PITCH + c + 1] = a[3];
                }
            }
        }
        __syncthreads();

        if (MODE == 1 || MODE == 2) {
            float* C = p.C + (size_t)blockIdx.z * p.sCz;
#pragma unroll
            for (int it = 0; it < 16; it++) {
                const int row = it * 4 + wid;
                const int gr = bm + h * 64 + row;
                float4 v = *(float4*)&smf[row * EPI_PITCH + lane * 4];
                if (MODE == 1) { v.x *= p.scale; v.y *= p.scale; v.z *= p.scale; v.w *= p.scale; }
                *(float4*)&C[(size_t)gr * p.ldc + bn + lane * 4] = v;
            }
        } else {
            if (bn < 2 * DIM) {                          // Q or K (row-major fp16)
                __half* dst = (bn < DIM) ? p.q : p.k;
                const int cb0 = (bn < DIM) ? bn : bn - DIM;
#pragma unroll
                for (int it = 0; it < 16; it++) {
                    const int row = it * 4 + wid;
                    const int gr = bm + h * 64 + row;
                    float4 v = *(float4*)&smf[row * EPI_PITCH + lane * 4];
                    __half2 h0 = __floats2half2_rn(v.x, v.y);
                    __half2 h1 = __floats2half2_rn(v.z, v.w);
                    uint2 u;
                    u.x = *reinterpret_cast<unsigned*>(&h0);
                    u.y = *reinterpret_cast<unsigned*>(&h1);
                    *(uint2*)&dst[(size_t)gr * DIM + cb0 + lane * 4] = u;
                }
            } else {                                     // V transposed: vt[b][d][i]
                const int d0 = bn - 2 * DIM;
                const int b  = bm >> 11;                 // tile never straddles batches
                const int i0 = (bm & (SEQ - 1)) + h * 64;
#pragma unroll
                for (int dd = 0; dd < 32; dd++) {
                    const int d = dd * 4 + wid;
                    const float f0 = smf[(lane * 2) * EPI_PITCH + d];
                    const float f1 = smf[(lane * 2 + 1) * EPI_PITCH + d];
                    __half2 hv = __floats2half2_rn(f0, f1);
                    *(__half2*)&p.vt[((size_t)b * DIM + d0 + d) * SEQ + i0 + lane * 2] = hv;
                }
            }
        }
        __syncthreads();
    }
}

// ---------------- prep: x -> fp16 hi/lo split ----------------
__global__ void convert_x_kernel(const float* __restrict__ x,
                                 __half* __restrict__ xh, __half* __restrict__ xl) {
    size_t i = (size_t)blockIdx.x * blockDim.x + threadIdx.x;
    float4 v = ((const float4*)x)[i];
    __half h0 = __float2half(v.x), h1 = __float2half(v.y);
    __half h2 = __float2half(v.z), h3 = __float2half(v.w);
    ((__half2*)xh)[2 * i]     = __halves2half2(h0, h1);
    ((__half2*)xh)[2 * i + 1] = __halves2half2(h2, h3);
    __half l0 = __float2half(v.x - __half2float(h0));
    __half l1 = __float2half(v.y - __half2float(h1));
    __half l2 = __float2half(v.z - __half2float(h2));
    __half l3 = __float2half(v.w - __half2float(h3));
    ((__half2*)xl)[2 * i]     = __halves2half2(l0, l1);
    ((__half2*)xl)[2 * i + 1] = __halves2half2(l2, l3);
}

// ---------------- prep: w[k][n] -> Wt[n][k] fp16 (tiled transpose) ----------------
__global__ void prep_w_kernel(const float* __restrict__ w, __half* __restrict__ wh) {
    __shared__ float t[32][33];
    const int k0 = blockIdx.y * 32, n0 = blockIdx.x * 32;
#pragma unroll
    for (int r = 0; r < 32; r += 8)
        t[threadIdx.y + r][threadIdx.x] =
            w[(size_t)(k0 + threadIdx.y + r) * DIM + n0 + threadIdx.x];
    __syncthreads();
#pragma unroll
    for (int r = 0; r < 32; r += 8) {
        const int n = n0 + threadIdx.y + r;
        const int k = k0 + threadIdx.x;
        wh[(size_t)n * DIM + k] = __float2half(t[threadIdx.x][threadIdx.y + r]);
    }
}

// ---------------- softmax: rows of 2048, fp32 in -> fp16 probs ----------------
__global__ __launch_bounds__(256) void softmax_kernel(const float* __restrict__ S,
                                                      __half* __restrict__ P) {
    __shared__ float red[8];
    const size_t row = blockIdx.x;
    const float* sr = S + row * SEQ;
    __half* pr = P + row * SEQ;
    const int tid = threadIdx.x;

    float v[8];
    float m = -1e30f;
#pragma unroll
    for (int j = 0; j < 8; j++) { v[j] = sr[tid + j * 256]; m = fmaxf(m, v[j]); }
#pragma unroll
    for (int o = 16; o > 0; o >>= 1) m = fmaxf(m, __shfl_xor_sync(0xffffffffu, m, o));
    if ((tid & 31) == 0) red[tid >> 5] = m;
    __syncthreads();
    float M = red[0];
#pragma unroll
    for (int wv = 1; wv < 8; wv++) M = fmaxf(M, red[wv]);
    __syncthreads();

    float sum = 0.0f;
#pragma unroll
    for (int j = 0; j < 8; j++) { v[j] = __expf(v[j] - M); sum += v[j]; }
#pragma unroll
    for (int o = 16; o > 0; o >>= 1) sum += __shfl_xor_sync(0xffffffffu, sum, o);
    if ((tid & 31) == 0) red[tid >> 5] = sum;
    __syncthreads();
    float tot = 0.0f;
#pragma unroll
    for (int wv = 0; wv < 8; wv++) tot += red[wv];
    const float inv = 1.0f / tot;
#pragma unroll
    for (int j = 0; j < 8; j++) pr[tid + j * 256] = __float2half(v[j] * inv);
}

// ---------------- launch ----------------
extern "C" void kernel_launch(void* const* d_in, const int* in_sizes, int n_in,
                              void* d_out, int out_size) {
    const float* x = (const float*)d_in[0];
    const float* w[3] = { (const float*)d_in[1], (const float*)d_in[2], (const float*)d_in[3] };
    float* out = (float*)d_out;

    void *xh, *xl, *wth, *q, *k, *vt, *s, *pbuf;
    cudaGetSymbolAddress(&xh, g_xh);
    cudaGetSymbolAddress(&xl, g_xl);
    cudaGetSymbolAddress(&wth, g_wth);
    cudaGetSymbolAddress(&q, g_q);
    cudaGetSymbolAddress(&k, g_k);
    cudaGetSymbolAddress(&vt, g_vt);
    cudaGetSymbolAddress(&s, g_s);
    cudaGetSymbolAddress(&pbuf, g_p);

    cudaFuncSetAttribute(gemm_kernel<0, true>,
                         cudaFuncAttributeMaxDynamicSharedMemorySize, SM_SPLIT);
    cudaFuncSetAttribute(gemm_kernel<1, false>,
                         cudaFuncAttributeMaxDynamicSharedMemorySize, SM_PLAIN);
    cudaFuncSetAttribute(gemm_kernel<2, false>,
                         cudaFuncAttributeMaxDynamicSharedMemorySize, SM_PLAIN);

    // 1) input split to fp16 hi/lo
    convert_x_kernel<<<(MTOK * DIM / 4) / 256, 256>>>(x, (__half*)xh, (__half*)xl);

    // 2) weight transpose to fp16 Wt[3072][1024]
    for (int i = 0; i < 3; i++)
        prep_w_kernel<<<dim3(32, 32), dim3(32, 8)>>>(
            w[i], (__half*)wth + (size_t)i * DIM * DIM);

    // 3) fused QKV projection: (xh + xl) * Wh  -> Q/K fp16 + V^T fp16
    {
        GemmP p{};
        p.A = (__half*)xh;  p.Al = (__half*)xl;
        p.B = (__half*)wth;
        p.q = (__half*)q; p.k = (__half*)k; p.vt = (__half*)vt;
        p.lda = DIM; p.ldb = DIM; p.K = DIM; p.scale = 1.0f;
        gemm_kernel<0, true><<<dim3(3 * DIM / BN, MTOK / BM, 1), 128, SM_SPLIT>>>(p);
    }

    // 4) scores = Q K^T / 32 (per batch)
    {
        GemmP p{};
        p.A = (__half*)q; p.B = (__half*)k; p.C = (float*)s;
        p.sAz = (long long)SEQ * DIM; p.sBz = (long long)SEQ * DIM;
        p.sCz = (long long)SEQ * SEQ;
        p.lda = DIM; p.ldb = DIM; p.ldc = SEQ; p.K = DIM;
        p.scale = 1.0f / 32.0f;
        gemm_kernel<1, false><<<dim3(SEQ / BN, SEQ / BM, BATCH), 128, SM_PLAIN>>>(p);
    }

    // 5) softmax rows -> fp16 P
    softmax_kernel<<<BATCH * SEQ, 256>>>((const float*)s, (__half*)pbuf);

    // 6) out = P V (per batch)
    {
        GemmP p{};
        p.A = (__half*)pbuf; p.B = (__half*)vt; p.C = out;
        p.sAz = (long long)SEQ * SEQ; p.sBz = (long long)DIM * SEQ;
        p.sCz = (long long)SEQ * DIM;
        p.lda = SEQ; p.ldb = SEQ; p.ldc = DIM; p.K = SEQ;
        p.scale = 1.0f;
        gemm_kernel<2, false><<<dim3(DIM / BN, SEQ / BM, BATCH), 128, SM_PLAIN>>>(p);
    }
}

// round 17
// speedup vs baseline: 1.9090x; 1.0011x over previous
#include <cuda_runtime.h>
#include <cuda_fp16.h>

#define DEV_INLINE __device__ __forceinline__

// ---------------- problem constants ----------------
constexpr int BATCH = 4;
constexpr int SEQ   = 2048;
constexpr int DIM   = 1024;            // D == DQKV
constexpr int MTOK  = BATCH * SEQ;     // 8192

// ---------------- GEMM tiling: 128x128x64 block, 4 warps of 64x64 ----------------
constexpr int BM = 128, BN = 128, BK = 64, SPAD = 8;
constexpr int LDS = BK + SPAD;                 // 72 halfs per smem row
constexpr int TILE_E = BM * LDS;               // 9216 elems per operand tile
constexpr int NKS = BK / 16;                   // 4 k16-steps per tile
constexpr int EPI_PITCH = 132;                 // fp32 words per staged row
constexpr int EPI_BYTES = 64 * EPI_PITCH * 4;  // 33792 (one 64-row half)
constexpr int SM_PLAIN = 2 * 2 * TILE_E * 2;   //  73728 B (A,B x 2 stages)
constexpr int SM_SPLIT = 2 * 3 * TILE_E * 2;   // 110592 B (Ah,Al,B x 2 stages)
static_assert(EPI_BYTES <= SM_PLAIN, "epilogue staging fits");

// ---------------- scratch (static device allocations; no cudaMalloc) ----------------
__device__ __align__(16) __half g_xh[MTOK * DIM];
__device__ __align__(16) __half g_xl[MTOK * DIM];
__device__ __align__(16) __half g_wth[3 * DIM * DIM];        // Wt[n][k] fp16
__device__ __align__(16) __half g_q[MTOK * DIM];
__device__ __align__(16) __half g_k[MTOK * DIM];
__device__ __align__(16) __half g_vt[BATCH * DIM * SEQ];     // V^T [b][d][i]
__device__ __align__(16) float  g_s[(size_t)BATCH * SEQ * SEQ];
__device__ __align__(16) __half g_p[(size_t)BATCH * SEQ * SEQ];

// ---------------- PTX helpers ----------------
DEV_INLINE void cp16(unsigned dst, const void* src) {
    asm volatile("cp.async.cg.shared.global [%0], [%1], 16;\n" :: "r"(dst), "l"(src));
}
DEV_INLINE void cp_commit() { asm volatile("cp.async.commit_group;\n" ::: "memory"); }
template <int N> DEV_INLINE void cp_wait() {
    asm volatile("cp.async.wait_group %0;\n" :: "n"(N) : "memory");
}
DEV_INLINE void ldsm4(unsigned addr, unsigned& r0, unsigned& r1, unsigned& r2, unsigned& r3) {
    asm volatile("ldmatrix.sync.aligned.m8n8.x4.shared.b16 {%0,%1,%2,%3}, [%4];\n"
        : "=r"(r0), "=r"(r1), "=r"(r2), "=r"(r3) : "r"(addr));
}
DEV_INLINE void mma16816(float c[4], const unsigned a[4], const unsigned b[2]) {
    asm volatile(
        "mma.sync.aligned.m16n8k16.row.col.f32.f16.f16.f32 "
        "{%0,%1,%2,%3}, {%4,%5,%6,%7}, {%8,%9}, {%0,%1,%2,%3};\n"
        : "+f"(c[0]), "+f"(c[1]), "+f"(c[2]), "+f"(c[3])
        : "r"(a[0]), "r"(a[1]), "r"(a[2]), "r"(a[3]), "r"(b[0]), "r"(b[1]));
}

// ---------------- GEMM parameter block ----------------
struct GemmP {
    const __half* A;  const __half* Al;     // Al used only when SPLIT
    const __half* B;
    float* C;
    __half* q; __half* k; __half* vt;
    long long sAz, sBz, sCz;                // per-batch (blockIdx.z) element strides
    int lda, ldb, ldc, K;
    float scale;
};

// MODE 0: QKV projection epilogue (fp16 Q/K row-major + V transposed)
// MODE 1: scores epilogue (fp32 * scale)
// MODE 2: output epilogue (fp32)
template <int MODE, bool SPLIT>
__global__ __launch_bounds__(128, 2) void gemm_kernel(GemmP p) {
    extern __shared__ char smraw[];
    const unsigned su = (unsigned)__cvta_generic_to_shared(smraw);
    constexpr int STAGE_B = (SPLIT ? 3 : 2) * TILE_E * 2;   // bytes per stage
    constexpr int BOFF = (SPLIT ? 2 : 1) * TILE_E * 2;      // B-tile byte offset in stage

    const int tid = threadIdx.x;
    const int lane = tid & 31, wid = tid >> 5;              // 4 warps
    const int bm = blockIdx.y * BM;
    const int bn = blockIdx.x * BN;

    const __half* A  = p.A + (size_t)blockIdx.z * p.sAz;
    const __half* B  = p.B + (size_t)blockIdx.z * p.sBz;
    const __half* Al = SPLIT ? (p.Al + (size_t)blockIdx.z * p.sAz) : nullptr;

    // gmem->smem: 128x64 halves per tile = 1024 16B chunks, 8 per thread
    auto load_tile = [&](const __half* G, int ld, int rbase, unsigned sbase, int k0) {
#pragma unroll
        for (int i = 0; i < 8; i++) {
            const int ch = tid + i * 128;                   // 0..1023
            const int row = ch >> 3, cc = (ch & 7) * 8;
            cp16(sbase + (unsigned)((row * LDS + cc) * 2),
                 G + (size_t)(rbase + row) * ld + k0 + cc);
        }
    };
    auto load_stage = [&](int st, int k0) {
        const unsigned uA = su + (unsigned)(st * STAGE_B);
        load_tile(A, p.lda, bm, uA, k0);
        if (SPLIT) load_tile(Al, p.lda, bm, uA + (unsigned)(TILE_E * 2), k0);
        load_tile(B, p.ldb, bn, uA + (unsigned)BOFF, k0);
    };

    const int wm0 = (wid & 1) * 64;     // 0 / 64
    const int wn0 = (wid >> 1) * 64;    // 0 / 64

    // A fragments: ldsm4 per m16 tile (4 tiles)
    int aoff[4];
#pragma unroll
    for (int mt = 0; mt < 4; mt++)
        aoff[mt] = (wm0 + mt * 16 + (lane & 15)) * LDS + ((lane >> 4) << 3);
    // B fragments: ldsm4 per n16 pair (4 pairs -> 8 n8 tiles)
    int boff[4];
#pragma unroll
    for (int np = 0; np < 4; np++)
        boff[np] = (wn0 + np * 16 + ((lane >> 4) << 3) + (lane & 7)) * LDS
                 + (((lane >> 3) & 1) << 3);

    float acc[4][8][4];
#pragma unroll
    for (int mt = 0; mt < 4; mt++)
#pragma unroll
        for (int nt = 0; nt < 8; nt++)
#pragma unroll
            for (int i = 0; i < 4; i++) acc[mt][nt][i] = 0.0f;

    const int KT = p.K / BK;
    load_stage(0, 0);
    cp_commit();

    for (int kt = 0; kt < KT; kt++) {
        if (kt + 1 < KT) {
            load_stage((kt + 1) & 1, (kt + 1) * BK);
            cp_commit();
            cp_wait<1>();
        } else {
            cp_wait<0>();
        }
        __syncthreads();

        const int st = kt & 1;
        const unsigned uA  = su + (unsigned)(st * STAGE_B);
        const unsigned uB  = uA + (unsigned)BOFF;
        const unsigned uAl = uA + (unsigned)(TILE_E * 2);

        // double-buffered fragment registers; afl single-buffered
        unsigned af[2][4][4], bf[2][8][2], afl[4][4];

        auto ld_frag = [&](int kk, int buf) {
#pragma unroll
            for (int mt = 0; mt < 4; mt++)
                ldsm4(uA + (unsigned)((aoff[mt] + kk) * 2),
                      af[buf][mt][0], af[buf][mt][1], af[buf][mt][2], af[buf][mt][3]);
#pragma unroll
            for (int np = 0; np < 4; np++)
                ldsm4(uB + (unsigned)((boff[np] + kk) * 2),
                      bf[buf][np * 2][0], bf[buf][np * 2][1],
                      bf[buf][np * 2 + 1][0], bf[buf][np * 2 + 1][1]);
        };

        ld_frag(0, 0);                      // prologue for this k-tile

#pragma unroll
        for (int ks = 0; ks < NKS; ks++) {
            const int kk = ks * 16;
            const int cur = ks & 1, nxt = cur ^ 1;
            if (SPLIT) {                    // issue afl loads early; hidden under hi-MMAs
#pragma unroll
                for (int mt = 0; mt < 4; mt++)
                    ldsm4(uAl + (unsigned)((aoff[mt] + kk) * 2),
                          afl[mt][0], afl[mt][1], afl[mt][2], afl[mt][3]);
            }
            if (ks + 1 < NKS) ld_frag(kk + 16, nxt);   // prefetch next step's fragments
#pragma unroll
            for (int mt = 0; mt < 4; mt++) {
#pragma unroll
                for (int nt = 0; nt < 8; nt++) {
                    mma16816(acc[mt][nt], af[cur][mt], bf[cur][nt]);
                    if (SPLIT) mma16816(acc[mt][nt], afl[mt], bf[cur][nt]);  // x_lo*w_hi
                }
            }
        }
        __syncthreads();
    }

    // ---------------- epilogue: stage 64x128 fp32 halves through smem ----------------
    float* smf = (float*)smraw;
    const int g = lane >> 2, tg = lane & 3;

#pragma unroll
    for (int h = 0; h < 2; h++) {
        if (wm0 == h * 64) {                // 2 warps per half (wid 0,2 / 1,3)
#pragma unroll
            for (int mt = 0; mt < 4; mt++) {
#pragma unroll
                for (int nt = 0; nt < 8; nt++) {
                    const int rl = mt * 16 + g;
                    const int c  = wn0 + nt * 8 + tg * 2;
                    const float* a = acc[mt][nt];
                    smf[rl * EPI_PITCH + c]           = a[0];
                    smf[rl * EPI_PITCH + c + 1]       = a[1];
                    smf[(rl + 8) * EPI_PITCH + c]     = a[2];
                    smf[(rl + 8) * EPI_PITCH + c + 1] = a[3];
                }
            }
        }
        __syncthreads();

        if (MODE == 1 || MODE == 2) {
            float* C = p.C + (size_t)blockIdx.z * p.sCz;
#pragma unroll
            for (int it = 0; it < 16; it++) {
                const int row = it * 4 + wid;
                const int gr = bm + h * 64 + row;
                float4 v = *(float4*)&smf[row * EPI_PITCH + lane * 4];
                if (MODE == 1) { v.x *= p.scale; v.y *= p.scale; v.z *= p.scale; v.w *= p.scale; }
                *(float4*)&C[(size_t)gr * p.ldc + bn + lane * 4] = v;
            }
        } else {
            if (bn < 2 * DIM) {                          // Q or K (row-major fp16)
                __half* dst = (bn < DIM) ? p.q : p.k;
                const int cb0 = (bn < DIM) ? bn : bn - DIM;
#pragma unroll
                for (int it = 0; it < 16; it++) {
                    const int row = it * 4 + wid;
                    const int gr = bm + h * 64 + row;
                    float4 v = *(float4*)&smf[row * EPI_PITCH + lane * 4];
                    __half2 h0 = __floats2half2_rn(v.x, v.y);
                    __half2 h1 = __floats2half2_rn(v.z, v.w);
                    uint2 u;
                    u.x = *reinterpret_cast<unsigned*>(&h0);
                    u.y = *reinterpret_cast<unsigned*>(&h1);
                    *(uint2*)&dst[(size_t)gr * DIM + cb0 + lane * 4] = u;
                }
            } else {                                     // V transposed: vt[b][d][i]
                const int d0 = bn - 2 * DIM;
                const int b  = bm >> 11;                 // tile never straddles batches
                const int i0 = (bm & (SEQ - 1)) + h * 64;
#pragma unroll
                for (int dd = 0; dd < 32; dd++) {
                    const int d = dd * 4 + wid;
                    const float f0 = smf[(lane * 2) * EPI_PITCH + d];
                    const float f1 = smf[(lane * 2 + 1) * EPI_PITCH + d];
                    __half2 hv = __floats2half2_rn(f0, f1);
                    *(__half2*)&p.vt[((size_t)b * DIM + d0 + d) * SEQ + i0 + lane * 2] = hv;
                }
            }
        }
        __syncthreads();
    }
}

// ---------------- prep: x -> fp16 hi/lo split ----------------
__global__ void convert_x_kernel(const float* __restrict__ x,
                                 __half* __restrict__ xh, __half* __restrict__ xl) {
    size_t i = (size_t)blockIdx.x * blockDim.x + threadIdx.x;
    float4 v = ((const float4*)x)[i];
    __half h0 = __float2half(v.x), h1 = __float2half(v.y);
    __half h2 = __float2half(v.z), h3 = __float2half(v.w);
    ((__half2*)xh)[2 * i]     = __halves2half2(h0, h1);
    ((__half2*)xh)[2 * i + 1] = __halves2half2(h2, h3);
    __half l0 = __float2half(v.x - __half2float(h0));
    __half l1 = __float2half(v.y - __half2float(h1));
    __half l2 = __float2half(v.z - __half2float(h2));
    __half l3 = __float2half(v.w - __half2float(h3));
    ((__half2*)xl)[2 * i]     = __halves2half2(l0, l1);
    ((__half2*)xl)[2 * i + 1] = __halves2half2(l2, l3);
}

// ---------------- prep: w[k][n] -> Wt[n][k] fp16 (tiled transpose) ----------------
__global__ void prep_w_kernel(const float* __restrict__ w, __half* __restrict__ wh) {
    __shared__ float t[32][33];
    const int k0 = blockIdx.y * 32, n0 = blockIdx.x * 32;
#pragma unroll
    for (int r = 0; r < 32; r += 8)
        t[threadIdx.y + r][threadIdx.x] =
            w[(size_t)(k0 + threadIdx.y + r) * DIM + n0 + threadIdx.x];
    __syncthreads();
#pragma unroll
    for (int r = 0; r < 32; r += 8) {
        const int n = n0 + threadIdx.y + r;
        const int k = k0 + threadIdx.x;
        wh[(size_t)n * DIM + k] = __float2half(t[threadIdx.x][threadIdx.y + r]);
    }
}

// ---------------- softmax: rows of 2048, fp32 in -> fp16 probs ----------------
__global__ __launch_bounds__(256) void softmax_kernel(const float* __restrict__ S,
                                                      __half* __restrict__ P) {
    __shared__ float red[8];
    const size_t row = blockIdx.x;
    const float* sr = S + row * SEQ;
    __half* pr = P + row * SEQ;
    const int tid = threadIdx.x;

    float v[8];
    float m = -1e30f;
#pragma unroll
    for (int j = 0; j < 8; j++) { v[j] = sr[tid + j * 256]; m = fmaxf(m, v[j]); }
#pragma unroll
    for (int o = 16; o > 0; o >>= 1) m = fmaxf(m, __shfl_xor_sync(0xffffffffu, m, o));
    if ((tid & 31) == 0) red[tid >> 5] = m;
    __syncthreads();
    float M = red[0];
#pragma unroll
    for (int wv = 1; wv < 8; wv++) M = fmaxf(M, red[wv]);
    __syncthreads();

    float sum = 0.0f;
#pragma unroll
    for (int j = 0; j < 8; j++) { v[j] = __expf(v[j] - M); sum += v[j]; }
#pragma unroll
    for (int o = 16; o > 0; o >>= 1) sum += __shfl_xor_sync(0xffffffffu, sum, o);
    if ((tid & 31) == 0) red[tid >> 5] = sum;
    __syncthreads();
    float tot = 0.0f;
#pragma unroll
    for (int wv = 0; wv < 8; wv++) tot += red[wv];
    const float inv = 1.0f / tot;
#pragma unroll
    for (int j = 0; j < 8; j++) pr[tid + j * 256] = __float2half(v[j] * inv);
}

// ---------------- launch ----------------
extern "C" void kernel_launch(void* const* d_in, const int* in_sizes, int n_in,
                              void* d_out, int out_size) {
    const float* x = (const float*)d_in[0];
    const float* w[3] = { (const float*)d_in[1], (const float*)d_in[2], (const float*)d_in[3] };
    float* out = (float*)d_out;

    void *xh, *xl, *wth, *q, *k, *vt, *s, *pbuf;
    cudaGetSymbolAddress(&xh, g_xh);
    cudaGetSymbolAddress(&xl, g_xl);
    cudaGetSymbolAddress(&wth, g_wth);
    cudaGetSymbolAddress(&q, g_q);
    cudaGetSymbolAddress(&k, g_k);
    cudaGetSymbolAddress(&vt, g_vt);
    cudaGetSymbolAddress(&s, g_s);
    cudaGetSymbolAddress(&pbuf, g_p);

    cudaFuncSetAttribute(gemm_kernel<0, true>,
                         cudaFuncAttributeMaxDynamicSharedMemorySize, SM_SPLIT);
    cudaFuncSetAttribute(gemm_kernel<1, false>,
                         cudaFuncAttributeMaxDynamicSharedMemorySize, SM_PLAIN);
    cudaFuncSetAttribute(gemm_kernel<2, false>,
                         cudaFuncAttributeMaxDynamicSharedMemorySize, SM_PLAIN);

    // 1) input split to fp16 hi/lo
    convert_x_kernel<<<(MTOK * DIM / 4) / 256, 256>>>(x, (__half*)xh, (__half*)xl);

    // 2) weight transpose to fp16 Wt[3072][1024]
    for (int i = 0; i < 3; i++)
        prep_w_kernel<<<dim3(32, 32), dim3(32, 8)>>>(
            w[i], (__half*)wth + (size_t)i * DIM * DIM);

    // 3) fused QKV projection: (xh + xl) * Wh  -> Q/K fp16 + V^T fp16
    {
        GemmP p{};
        p.A = (__half*)xh;  p.Al = (__half*)xl;
        p.B = (__half*)wth;
        p.q = (__half*)q; p.k = (__half*)k; p.vt = (__half*)vt;
        p.lda = DIM; p.ldb = DIM; p.K = DIM; p.scale = 1.0f;
        gemm_kernel<0, true><<<dim3(3 * DIM / BN, MTOK / BM, 1), 128, SM_SPLIT>>>(p);
    }

    // 4) scores = Q K^T / 32 (per batch)
    {
        GemmP p{};
        p.A = (__half*)q; p.B = (__half*)k; p.C = (float*)s;
        p.sAz = (long long)SEQ * DIM; p.sBz = (long long)SEQ * DIM;
        p.sCz = (long long)SEQ * SEQ;
        p.lda = DIM; p.ldb = DIM; p.ldc = SEQ; p.K = DIM;
        p.scale = 1.0f / 32.0f;
        gemm_kernel<1, false><<<dim3(SEQ / BN, SEQ / BM, BATCH), 128, SM_PLAIN>>>(p);
    }

    // 5) softmax rows -> fp16 P
    softmax_kernel<<<BATCH * SEQ, 256>>>((const float*)s, (__half*)pbuf);

    // 6) out = P V (per batch)
    {
        GemmP p{};
        p.A = (__half*)pbuf; p.B = (__half*)vt; p.C = out;
        p.sAz = (long long)SEQ * SEQ; p.sBz = (long long)DIM * SEQ;
        p.sCz = (long long)SEQ * DIM;
        p.lda = SEQ; p.ldb = SEQ; p.ldc = DIM; p.K = SEQ;
        p.scale = 1.0f;
        gemm_kernel<2, false><<<dim3(DIM / BN, SEQ / BM, BATCH), 128, SM_PLAIN>>>(p);
    }
}